// round 1
// baseline (speedup 1.0000x reference)
#include <cuda_runtime.h>
#include <cuda_bf16.h>
#include <math.h>

// Problem constants
#define FRAMES  256
#define PATCHES 64
#define DIM     512
#define HEADS   8
#define DH      64
#define DFF     1024
#define KL      128      // Linformer projection length
#define TT      257      // temporal tokens (1 + FRAMES)
#define TS      65       // spatial tokens (1 + PATCHES)
#define RT      (PATCHES * TT)   // 16448 temporal rows
#define RS      (FRAMES * TS)    // 16640 spatial rows

#define FLAG_BIAS 1
#define FLAG_RES  2
#define FLAG_GELU 4

// -------------------- scratch (device globals; no allocation allowed) -----
__device__ float g_xt   [RT * DIM];          // temporal input (with cls)
__device__ float g_qkv  [RS * 3 * DIM];      // qkv (reused temporal/spatial)
__device__ float g_attn [RS * DIM];          // attention output (reused)
__device__ float g_yt   [RT * DIM];          // temporal block output
__device__ float g_ys   [RS * DIM];          // spatial input (with cls)
__device__ float g_ys2  [RS * DIM];          // spatial block output
__device__ float g_kproj[FRAMES * KL * DIM];
__device__ float g_vproj[FRAMES * KL * DIM];
__device__ float g_h    [RS * DFF];          // MLP hidden

// -------------------- generic tiled fp32 GEMM with fused epilogue ---------
// C[M,N] = A[M,K] @ B[K,N]  (+bias) (+gelu) (+residual R)
// Requires M%64==0, N%64==0, K%16==0 (true for all shapes here).
__global__ __launch_bounds__(256) void gemm_ep(
    const float* __restrict__ A, const float* __restrict__ B,
    const float* __restrict__ bias, const float* __restrict__ R,
    float* __restrict__ C, int M, int N, int K, int flags)
{
    __shared__ float As[16][64];
    __shared__ float Bs[16][64];

    int tid = threadIdx.x;
    int tx = tid & 15, ty = tid >> 4;
    int r0 = blockIdx.y * 64, c0 = blockIdx.x * 64;

    float acc[4][4];
    #pragma unroll
    for (int i = 0; i < 4; i++)
        #pragma unroll
        for (int j = 0; j < 4; j++) acc[i][j] = 0.0f;

    int arow = tid >> 2;            // 0..63
    int acol = (tid & 3) * 4;       // 0,4,8,12
    int brow = tid >> 4;            // 0..15
    int bcol = (tid & 15) * 4;      // 0..60

    for (int k0 = 0; k0 < K; k0 += 16) {
        float4 av = *(const float4*)&A[(size_t)(r0 + arow) * K + k0 + acol];
        As[acol + 0][arow] = av.x;
        As[acol + 1][arow] = av.y;
        As[acol + 2][arow] = av.z;
        As[acol + 3][arow] = av.w;
        *(float4*)&Bs[brow][bcol] =
            *(const float4*)&B[(size_t)(k0 + brow) * N + c0 + bcol];
        __syncthreads();

        #pragma unroll
        for (int kk = 0; kk < 16; kk++) {
            float4 a = *(float4*)&As[kk][ty * 4];
            float4 b = *(float4*)&Bs[kk][tx * 4];
            float ar[4] = {a.x, a.y, a.z, a.w};
            float br[4] = {b.x, b.y, b.z, b.w};
            #pragma unroll
            for (int i = 0; i < 4; i++)
                #pragma unroll
                for (int j = 0; j < 4; j++)
                    acc[i][j] += ar[i] * br[j];
        }
        __syncthreads();
    }

    #pragma unroll
    for (int i = 0; i < 4; i++) {
        int row = r0 + ty * 4 + i;
        #pragma unroll
        for (int j = 0; j < 4; j++) {
            int col = c0 + tx * 4 + j;
            float v = acc[i][j];
            if (flags & FLAG_BIAS) v += bias[col];
            if (flags & FLAG_GELU) v = 0.5f * v * (1.0f + erff(v * 0.70710678118654752f));
            if (flags & FLAG_RES)  v += R[(size_t)row * N + col];
            C[(size_t)row * N + col] = v;
        }
    }
}

// -------------------- fused attention (one block per (batch, head)) -------
// K/V staged in SMEM with row stride 65 (bank-conflict free).
// Warp-per-query-row softmax; lanes own output dims for AV.
__global__ __launch_bounds__(256) void attn_kernel(
    const float* __restrict__ Q, int qStride,
    const float* __restrict__ Kp, const float* __restrict__ Vp, int kvStride,
    float* __restrict__ O, int Tq, int Tk, float scale)
{
    extern __shared__ float sm[];
    float* Ks    = sm;                       // Tk * 65
    float* Vs    = Ks + Tk * 65;             // Tk * 65
    float* probs = Vs + Tk * 65;             // 8 * Tk
    float* qr    = probs + 8 * Tk;           // 8 * 64

    int b = blockIdx.x, h = blockIdx.y;
    int tid = threadIdx.x;
    int w = tid >> 5, lane = tid & 31;

    const float* Qb = Q  + (size_t)b * Tq * qStride  + h * DH;
    const float* Kb = Kp + (size_t)b * Tk * kvStride + h * DH;
    const float* Vb = Vp + (size_t)b * Tk * kvStride + h * DH;
    float* Ob = O + (size_t)b * Tq * DIM + h * DH;

    for (int i = tid; i < Tk * DH; i += 256) {
        int r = i >> 6, c = i & 63;
        Ks[r * 65 + c] = Kb[(size_t)r * kvStride + c];
        Vs[r * 65 + c] = Vb[(size_t)r * kvStride + c];
    }
    __syncthreads();

    for (int r = w; r < Tq; r += 8) {
        qr[w * 64 + lane]      = Qb[(size_t)r * qStride + lane];
        qr[w * 64 + 32 + lane] = Qb[(size_t)r * qStride + 32 + lane];
        __syncwarp();

        float lmax = -1e30f;
        for (int j = lane; j < Tk; j += 32) {
            float s = 0.0f;
            #pragma unroll
            for (int d = 0; d < DH; d++)
                s += qr[w * 64 + d] * Ks[j * 65 + d];
            s *= scale;
            probs[w * Tk + j] = s;
            lmax = fmaxf(lmax, s);
        }
        #pragma unroll
        for (int off = 16; off > 0; off >>= 1)
            lmax = fmaxf(lmax, __shfl_xor_sync(0xffffffffu, lmax, off));

        float lsum = 0.0f;
        for (int j = lane; j < Tk; j += 32) {
            float e = __expf(probs[w * Tk + j] - lmax);
            probs[w * Tk + j] = e;
            lsum += e;
        }
        #pragma unroll
        for (int off = 16; off > 0; off >>= 1)
            lsum += __shfl_xor_sync(0xffffffffu, lsum, off);
        float inv = 1.0f / lsum;
        __syncwarp();

        float a0 = 0.0f, a1 = 0.0f;
        for (int j = 0; j < Tk; j++) {
            float p = probs[w * Tk + j];
            a0 += p * Vs[j * 65 + lane];
            a1 += p * Vs[j * 65 + 32 + lane];
        }
        Ob[(size_t)r * DIM + lane]      = a0 * inv;
        Ob[(size_t)r * DIM + 32 + lane] = a1 * inv;
        __syncwarp();
    }
}

// -------------------- Linformer K/V projection -----------------------------
// kproj[b][kk][c] = sum_j qkv[b*65+j][512(+512 for V) + c] * E[j][kk]
__global__ __launch_bounds__(256) void linproj_kernel(
    const float* __restrict__ qkv, const float* __restrict__ E,
    float* __restrict__ kproj, float* __restrict__ vproj)
{
    __shared__ float Es[TS * 32];   // E[j][kkt*32 + q]
    __shared__ float Ksm[TS * 64];  // qkv tile [j][c]

    int b = blockIdx.x;
    int c0 = blockIdx.y * 64;
    int zz = blockIdx.z;
    int kvsel = zz & 1;
    int kkt = zz >> 1;              // 0..3
    int tid = threadIdx.x;

    int colbase = DIM + kvsel * DIM + c0;
    for (int i = tid; i < TS * 64; i += 256) {
        int j = i >> 6, c = i & 63;
        Ksm[i] = qkv[((size_t)b * TS + j) * (3 * DIM) + colbase + c];
    }
    for (int i = tid; i < TS * 32; i += 256) {
        int j = i >> 5, q = i & 31;
        Es[i] = E[j * KL + kkt * 32 + q];
    }
    __syncthreads();

    int c = tid & 63, kg = tid >> 6;   // kg 0..3
    float acc[8];
    #pragma unroll
    for (int i = 0; i < 8; i++) acc[i] = 0.0f;

    for (int j = 0; j < TS; j++) {
        float kv = Ksm[j * 64 + c];
        #pragma unroll
        for (int i = 0; i < 8; i++)
            acc[i] += kv * Es[j * 32 + kg * 8 + i];
    }

    float* dst = kvsel ? vproj : kproj;
    #pragma unroll
    for (int i = 0; i < 8; i++) {
        int kk = kkt * 32 + kg * 8 + i;
        dst[((size_t)b * KL + kk) * DIM + c0 + c] = acc[i];
    }
}

// -------------------- token rearrangement ---------------------------------
__global__ void gather_t_kernel(const float* __restrict__ x, float* __restrict__ xt)
{
    int row = blockIdx.x;              // 0..RT-1
    int p = row / TT, t = row % TT;
    const float4* s = (const float4*)(t == 0 ? x
                        : x + (size_t)(1 + (t - 1) * PATCHES + p) * DIM);
    float4* d = (float4*)(xt + (size_t)row * DIM);
    d[threadIdx.x] = s[threadIdx.x];
}

__global__ void gather_s_kernel(const float* __restrict__ yt, float* __restrict__ ys)
{
    int row = blockIdx.x;              // 0..RS-1
    int f = row / TS, t = row % TS;
    const float* src = (t == 0)
        ? yt + (size_t)((f & 63) * TT) * DIM               // cls2[f % 64]
        : yt + (size_t)((t - 1) * TT + 1 + f) * DIM;       // y_t[p][1+f]
    ((float4*)(ys + (size_t)row * DIM))[threadIdx.x] = ((const float4*)src)[threadIdx.x];
}

// -------------------- launch ----------------------------------------------
extern "C" void kernel_launch(void* const* d_in, const int* in_sizes, int n_in,
                              void* d_out, int out_size)
{
    const float* x      = (const float*)d_in[0];
    const float* Wqkv_t = (const float*)d_in[1];
    const float* Wo_t   = (const float*)d_in[2];
    const float* Wqkv_s = (const float*)d_in[3];
    const float* Wo_s   = (const float*)d_in[4];
    const float* E      = (const float*)d_in[5];
    const float* W1     = (const float*)d_in[6];
    const float* b1     = (const float*)d_in[7];
    const float* W2     = (const float*)d_in[8];
    const float* b2     = (const float*)d_in[9];
    float* out = (float*)d_out;

    float *xt, *qkv, *attn, *yt, *ys, *ys2, *kproj, *vproj, *hbuf;
    cudaGetSymbolAddress((void**)&xt,    g_xt);
    cudaGetSymbolAddress((void**)&qkv,   g_qkv);
    cudaGetSymbolAddress((void**)&attn,  g_attn);
    cudaGetSymbolAddress((void**)&yt,    g_yt);
    cudaGetSymbolAddress((void**)&ys,    g_ys);
    cudaGetSymbolAddress((void**)&ys2,   g_ys2);
    cudaGetSymbolAddress((void**)&kproj, g_kproj);
    cudaGetSymbolAddress((void**)&vproj, g_vproj);
    cudaGetSymbolAddress((void**)&hbuf,  g_h);

    // Dynamic smem for attention (temporal case is the max): 143,912 B
    int smemT = (2 * TT * 65 + 8 * TT + 8 * 64) * (int)sizeof(float);
    int smemS = (2 * KL * 65 + 8 * KL + 8 * 64) * (int)sizeof(float);
    cudaFuncSetAttribute(attn_kernel, cudaFuncAttributeMaxDynamicSharedMemorySize, smemT);

    // 1) temporal token gather (prepend cls to each of 64 patch sequences)
    gather_t_kernel<<<RT, 128>>>(x, xt);

    // 2) temporal QKV: [16448,512] @ [512,1536]
    gemm_ep<<<dim3(3 * DIM / 64, RT / 64), 256>>>(xt, Wqkv_t, nullptr, nullptr,
                                                  qkv, RT, 3 * DIM, DIM, 0);

    // 3) temporal attention (Tq=Tk=257)
    attn_kernel<<<dim3(PATCHES, HEADS), 256, smemT>>>(
        qkv, 3 * DIM, qkv + DIM, qkv + 2 * DIM, 3 * DIM, attn, TT, TT, 0.125f);

    // 4) Wo_t + residual
    gemm_ep<<<dim3(DIM / 64, RT / 64), 256>>>(attn, Wo_t, nullptr, xt,
                                              yt, RT, DIM, DIM, FLAG_RES);

    // 5) spatial token gather
    gather_s_kernel<<<RS, 128>>>(yt, ys);

    // 6) spatial QKV: [16640,512] @ [512,1536]
    gemm_ep<<<dim3(3 * DIM / 64, RS / 64), 256>>>(ys, Wqkv_s, nullptr, nullptr,
                                                  qkv, RS, 3 * DIM, DIM, 0);

    // 7) Linformer K/V projection via E
    linproj_kernel<<<dim3(FRAMES, DIM / 64, 8), 256>>>(qkv, E, kproj, vproj);

    // 8) spatial attention (Tq=65, Tk=128)
    attn_kernel<<<dim3(FRAMES, HEADS), 256, smemS>>>(
        qkv, 3 * DIM, kproj, vproj, DIM, attn, TS, KL, 0.125f);

    // 9) Wo_s + residual
    gemm_ep<<<dim3(DIM / 64, RS / 64), 256>>>(attn, Wo_s, nullptr, ys,
                                              ys2, RS, DIM, DIM, FLAG_RES);

    // 10) MLP up + bias + exact GELU
    gemm_ep<<<dim3(DFF / 64, RS / 64), 256>>>(ys2, W1, b1, nullptr,
                                              hbuf, RS, DFF, DIM, FLAG_BIAS | FLAG_GELU);

    // 11) MLP down + bias + residual -> final output
    gemm_ep<<<dim3(DIM / 64, RS / 64), 256>>>(hbuf, W2, b2, ys2,
                                              out, RS, DIM, DFF, FLAG_BIAS | FLAG_RES);
}

// round 3
// speedup vs baseline: 1.3132x; 1.3132x over previous
#include <cuda_runtime.h>
#include <cuda_bf16.h>
#include <math.h>
#include <stdint.h>

// Problem constants
#define FRAMES  256
#define PATCHES 64
#define DIM     512
#define HEADS   8
#define DH      64
#define DFF     1024
#define KL      128
#define TT      257
#define TS      65
#define RT      (PATCHES * TT)   // 16448
#define RS      (FRAMES * TS)    // 16640

#define FLAG_BIAS 1
#define FLAG_RES  2
#define FLAG_GELU 4

// -------------------- scratch --------------------------------------------
__device__ float g_xt   [RT * DIM];
__device__ float g_qkv  [RS * 3 * DIM];
__device__ float g_attn [RS * DIM];
__device__ float g_yt   [RT * DIM];
__device__ float g_ys   [RS * DIM];
__device__ float g_ys2  [RS * DIM];
__device__ float g_kproj[FRAMES * KL * DIM];
__device__ float g_vproj[FRAMES * KL * DIM];
__device__ float g_h    [RS * DFF];

// -------------------- tf32 helpers ---------------------------------------
__device__ __forceinline__ float f2tf32(float x) {
    uint32_t u;
    asm("cvt.rna.tf32.f32 %0, %1;" : "=r"(u) : "f"(x));
    return __uint_as_float(u);
}

__device__ __forceinline__ void mma_tf32(float (&c)[4], const uint32_t (&a)[4],
                                         const uint32_t (&b)[2]) {
    asm volatile(
        "mma.sync.aligned.m16n8k8.row.col.f32.tf32.tf32.f32 "
        "{%0,%1,%2,%3}, {%4,%5,%6,%7}, {%8,%9}, {%0,%1,%2,%3};"
        : "+f"(c[0]), "+f"(c[1]), "+f"(c[2]), "+f"(c[3])
        : "r"(a[0]), "r"(a[1]), "r"(a[2]), "r"(a[3]), "r"(b[0]), "r"(b[1]));
}

// -------------------- tf32 tensor-core GEMM ------------------------------
// C[M,N] = A[M,K] @ B[K,N] (+bias)(+gelu)(+residual). M%64==0, N%128==0, K%16==0.
#define GBM 64
#define GBN 128
#define GBK 16
#define ASTR (GBM + 4)   // 68
#define BSTR (GBN + 4)   // 132

__global__ __launch_bounds__(256) void gemm_tc(
    const float* __restrict__ A, const float* __restrict__ B,
    const float* __restrict__ bias, const float* __restrict__ R,
    float* __restrict__ C, int M, int N, int K, int flags)
{
    __shared__ float As[2][GBK][ASTR];
    __shared__ float Bs[2][GBK][BSTR];

    int tid = threadIdx.x;
    int warp = tid >> 5, lane = tid & 31;
    int wr = warp & 1;            // warp row (0..1): 32 rows each
    int wc = warp >> 1;           // warp col (0..3): 32 cols each
    int r0 = blockIdx.y * GBM;
    int c0 = blockIdx.x * GBN;
    int g  = lane >> 2;           // group 0..7
    int tg = lane & 3;            // 0..3

    float acc[2][4][4];
    #pragma unroll
    for (int mt = 0; mt < 2; mt++)
        #pragma unroll
        for (int nt = 0; nt < 4; nt++)
            #pragma unroll
            for (int i = 0; i < 4; i++) acc[mt][nt][i] = 0.0f;

    int arow = tid >> 2;              // 0..63
    int acol = (tid & 3) * 4;         // 0,4,8,12
    int br0  = tid >> 5;              // 0..7
    int bc0  = (tid & 31) * 4;        // 0..124

    // prologue load tile 0
    {
        float4 av = *(const float4*)&A[(size_t)(r0 + arow) * K + acol];
        As[0][acol + 0][arow] = f2tf32(av.x);
        As[0][acol + 1][arow] = f2tf32(av.y);
        As[0][acol + 2][arow] = f2tf32(av.z);
        As[0][acol + 3][arow] = f2tf32(av.w);
        float4 b0 = *(const float4*)&B[(size_t)br0 * N + c0 + bc0];
        float4 b1 = *(const float4*)&B[(size_t)(br0 + 8) * N + c0 + bc0];
        float4 t0 = make_float4(f2tf32(b0.x), f2tf32(b0.y), f2tf32(b0.z), f2tf32(b0.w));
        float4 t1 = make_float4(f2tf32(b1.x), f2tf32(b1.y), f2tf32(b1.z), f2tf32(b1.w));
        *(float4*)&Bs[0][br0][bc0]     = t0;
        *(float4*)&Bs[0][br0 + 8][bc0] = t1;
    }
    __syncthreads();

    int buf = 0;
    for (int k0 = 0; k0 < K; k0 += GBK) {
        // prefetch next tile into buf^1
        if (k0 + GBK < K) {
            int kn = k0 + GBK;
            float4 av = *(const float4*)&A[(size_t)(r0 + arow) * K + kn + acol];
            As[buf ^ 1][acol + 0][arow] = f2tf32(av.x);
            As[buf ^ 1][acol + 1][arow] = f2tf32(av.y);
            As[buf ^ 1][acol + 2][arow] = f2tf32(av.z);
            As[buf ^ 1][acol + 3][arow] = f2tf32(av.w);
            float4 b0 = *(const float4*)&B[(size_t)(kn + br0) * N + c0 + bc0];
            float4 b1 = *(const float4*)&B[(size_t)(kn + br0 + 8) * N + c0 + bc0];
            float4 t0 = make_float4(f2tf32(b0.x), f2tf32(b0.y), f2tf32(b0.z), f2tf32(b0.w));
            float4 t1 = make_float4(f2tf32(b1.x), f2tf32(b1.y), f2tf32(b1.z), f2tf32(b1.w));
            *(float4*)&Bs[buf ^ 1][br0][bc0]     = t0;
            *(float4*)&Bs[buf ^ 1][br0 + 8][bc0] = t1;
        }

        // compute on buf
        #pragma unroll
        for (int kk = 0; kk < GBK; kk += 8) {
            uint32_t afrag[2][4];
            #pragma unroll
            for (int mt = 0; mt < 2; mt++) {
                int rb = wr * 32 + mt * 16;
                afrag[mt][0] = __float_as_uint(As[buf][kk + tg][rb + g]);
                afrag[mt][1] = __float_as_uint(As[buf][kk + tg][rb + g + 8]);
                afrag[mt][2] = __float_as_uint(As[buf][kk + tg + 4][rb + g]);
                afrag[mt][3] = __float_as_uint(As[buf][kk + tg + 4][rb + g + 8]);
            }
            uint32_t bfrag[4][2];
            #pragma unroll
            for (int nt = 0; nt < 4; nt++) {
                int cb = wc * 32 + nt * 8;
                bfrag[nt][0] = __float_as_uint(Bs[buf][kk + tg][cb + g]);
                bfrag[nt][1] = __float_as_uint(Bs[buf][kk + tg + 4][cb + g]);
            }
            #pragma unroll
            for (int mt = 0; mt < 2; mt++)
                #pragma unroll
                for (int nt = 0; nt < 4; nt++)
                    mma_tf32(acc[mt][nt], afrag[mt], bfrag[nt]);
        }
        __syncthreads();
        buf ^= 1;
    }

    // epilogue
    #pragma unroll
    for (int mt = 0; mt < 2; mt++) {
        #pragma unroll
        for (int nt = 0; nt < 4; nt++) {
            int col = c0 + wc * 32 + nt * 8 + 2 * tg;
            #pragma unroll
            for (int half = 0; half < 2; half++) {
                int row = r0 + wr * 32 + mt * 16 + g + half * 8;
                float v0 = acc[mt][nt][half * 2 + 0];
                float v1 = acc[mt][nt][half * 2 + 1];
                if (flags & FLAG_BIAS) { v0 += bias[col]; v1 += bias[col + 1]; }
                if (flags & FLAG_GELU) {
                    v0 = 0.5f * v0 * (1.0f + erff(v0 * 0.70710678118654752f));
                    v1 = 0.5f * v1 * (1.0f + erff(v1 * 0.70710678118654752f));
                }
                if (flags & FLAG_RES) {
                    float2 rr = *(const float2*)&R[(size_t)row * N + col];
                    v0 += rr.x; v1 += rr.y;
                }
                *(float2*)&C[(size_t)row * N + col] = make_float2(v0, v1);
            }
        }
    }
}

// -------------------- fused attention ------------------------------------
// K in SMEM (stride 68, float4-aligned, conflict-free), V streamed via L1.
#define KST 68
__global__ __launch_bounds__(256) void attn_kernel(
    const float* __restrict__ Q, int qStride,
    const float* __restrict__ Kp, const float* __restrict__ Vp, int kvStride,
    float* __restrict__ O, int Tq, int Tk, float scale)
{
    extern __shared__ float sm[];
    float* Ks    = sm;                   // Tk * KST
    float* probs = Ks + Tk * KST;        // 8 * Tk
    float* qr    = probs + 8 * Tk;       // 8 * 64

    int b = blockIdx.x, h = blockIdx.y;
    int tid = threadIdx.x;
    int w = tid >> 5, lane = tid & 31;

    const float* Qb = Q  + (size_t)b * Tq * qStride  + h * DH;
    const float* Kb = Kp + (size_t)b * Tk * kvStride + h * DH;
    const float* Vb = Vp + (size_t)b * Tk * kvStride + h * DH;
    float* Ob = O + (size_t)b * Tq * DIM + h * DH;

    for (int i = tid; i < Tk * DH; i += 256) {
        int r = i >> 6, c = i & 63;
        Ks[r * KST + c] = Kb[(size_t)r * kvStride + c];
    }
    __syncthreads();

    for (int r = w; r < Tq; r += 8) {
        qr[w * 64 + lane]      = Qb[(size_t)r * qStride + lane];
        qr[w * 64 + 32 + lane] = Qb[(size_t)r * qStride + 32 + lane];
        __syncwarp();

        const float4* q4 = (const float4*)&qr[w * 64];
        float lmax = -1e30f;
        for (int j = lane; j < Tk; j += 32) {
            const float4* k4 = (const float4*)&Ks[j * KST];
            float s = 0.0f;
            #pragma unroll
            for (int d4 = 0; d4 < 16; d4++) {
                float4 qv = q4[d4];
                float4 kv = k4[d4];
                s += qv.x * kv.x + qv.y * kv.y + qv.z * kv.z + qv.w * kv.w;
            }
            s *= scale;
            probs[w * Tk + j] = s;
            lmax = fmaxf(lmax, s);
        }
        #pragma unroll
        for (int off = 16; off > 0; off >>= 1)
            lmax = fmaxf(lmax, __shfl_xor_sync(0xffffffffu, lmax, off));

        float lsum = 0.0f;
        for (int j = lane; j < Tk; j += 32) {
            float e = __expf(probs[w * Tk + j] - lmax);
            probs[w * Tk + j] = e;
            lsum += e;
        }
        #pragma unroll
        for (int off = 16; off > 0; off >>= 1)
            lsum += __shfl_xor_sync(0xffffffffu, lsum, off);
        float inv = 1.0f / lsum;
        __syncwarp();

        float a0 = 0.0f, a1 = 0.0f;
        #pragma unroll 4
        for (int j = 0; j < Tk; j++) {
            float p = probs[w * Tk + j];
            a0 += p * __ldg(&Vb[(size_t)j * kvStride + lane]);
            a1 += p * __ldg(&Vb[(size_t)j * kvStride + 32 + lane]);
        }
        Ob[(size_t)r * DIM + lane]      = a0 * inv;
        Ob[(size_t)r * DIM + 32 + lane] = a1 * inv;
        __syncwarp();
    }
}

// -------------------- Linformer K/V projection ----------------------------
__global__ __launch_bounds__(256) void linproj_kernel(
    const float* __restrict__ qkv, const float* __restrict__ E,
    float* __restrict__ kproj, float* __restrict__ vproj)
{
    __shared__ float Es[TS * 32];
    __shared__ float Ksm[TS * 64];

    int b = blockIdx.x;
    int c0 = blockIdx.y * 64;
    int zz = blockIdx.z;
    int kvsel = zz & 1;
    int kkt = zz >> 1;
    int tid = threadIdx.x;

    int colbase = DIM + kvsel * DIM + c0;
    for (int i = tid; i < TS * 64; i += 256) {
        int j = i >> 6, c = i & 63;
        Ksm[i] = qkv[((size_t)b * TS + j) * (3 * DIM) + colbase + c];
    }
    for (int i = tid; i < TS * 32; i += 256) {
        int j = i >> 5, q = i & 31;
        Es[i] = E[j * KL + kkt * 32 + q];
    }
    __syncthreads();

    int c = tid & 63, kg = tid >> 6;
    float acc[8];
    #pragma unroll
    for (int i = 0; i < 8; i++) acc[i] = 0.0f;

    for (int j = 0; j < TS; j++) {
        float kv = Ksm[j * 64 + c];
        #pragma unroll
        for (int i = 0; i < 8; i++)
            acc[i] += kv * Es[j * 32 + kg * 8 + i];
    }

    float* dst = kvsel ? vproj : kproj;
    #pragma unroll
    for (int i = 0; i < 8; i++) {
        int kk = kkt * 32 + kg * 8 + i;
        dst[((size_t)b * KL + kk) * DIM + c0 + c] = acc[i];
    }
}

// -------------------- token rearrangement ---------------------------------
__global__ void gather_t_kernel(const float* __restrict__ x, float* __restrict__ xt)
{
    int row = blockIdx.x;
    int p = row / TT, t = row % TT;
    const float4* s = (const float4*)(t == 0 ? x
                        : x + (size_t)(1 + (t - 1) * PATCHES + p) * DIM);
    float4* d = (float4*)(xt + (size_t)row * DIM);
    d[threadIdx.x] = s[threadIdx.x];
}

__global__ void gather_s_kernel(const float* __restrict__ yt, float* __restrict__ ys)
{
    int row = blockIdx.x;
    int f = row / TS, t = row % TS;
    const float* src = (t == 0)
        ? yt + (size_t)((f & 63) * TT) * DIM
        : yt + (size_t)((t - 1) * TT + 1 + f) * DIM;
    ((float4*)(ys + (size_t)row * DIM))[threadIdx.x] = ((const float4*)src)[threadIdx.x];
}

// -------------------- launch ----------------------------------------------
extern "C" void kernel_launch(void* const* d_in, const int* in_sizes, int n_in,
                              void* d_out, int out_size)
{
    const float* x      = (const float*)d_in[0];
    const float* Wqkv_t = (const float*)d_in[1];
    const float* Wo_t   = (const float*)d_in[2];
    const float* Wqkv_s = (const float*)d_in[3];
    const float* Wo_s   = (const float*)d_in[4];
    const float* E      = (const float*)d_in[5];
    const float* W1     = (const float*)d_in[6];
    const float* b1     = (const float*)d_in[7];
    const float* W2     = (const float*)d_in[8];
    const float* b2     = (const float*)d_in[9];
    float* out = (float*)d_out;

    float *xt, *qkv, *attn, *yt, *ys, *ys2, *kproj, *vproj, *hbuf;
    cudaGetSymbolAddress((void**)&xt,    g_xt);
    cudaGetSymbolAddress((void**)&qkv,   g_qkv);
    cudaGetSymbolAddress((void**)&attn,  g_attn);
    cudaGetSymbolAddress((void**)&yt,    g_yt);
    cudaGetSymbolAddress((void**)&ys,    g_ys);
    cudaGetSymbolAddress((void**)&ys2,   g_ys2);
    cudaGetSymbolAddress((void**)&kproj, g_kproj);
    cudaGetSymbolAddress((void**)&vproj, g_vproj);
    cudaGetSymbolAddress((void**)&hbuf,  g_h);

    int smemT = (TT * KST + 8 * TT + 8 * 64) * (int)sizeof(float);   // ~80 KB
    int smemS = (KL * KST + 8 * KL + 8 * 64) * (int)sizeof(float);   // ~41 KB
    static int configured = 0;
    cudaFuncSetAttribute(attn_kernel, cudaFuncAttributeMaxDynamicSharedMemorySize, smemT);
    (void)configured;

    // 1) temporal token gather
    gather_t_kernel<<<RT, 128>>>(x, xt);

    // 2) temporal QKV
    gemm_tc<<<dim3(3 * DIM / GBN, RT / GBM), 256>>>(xt, Wqkv_t, nullptr, nullptr,
                                                    qkv, RT, 3 * DIM, DIM, 0);

    // 3) temporal attention
    attn_kernel<<<dim3(PATCHES, HEADS), 256, smemT>>>(
        qkv, 3 * DIM, qkv + DIM, qkv + 2 * DIM, 3 * DIM, attn, TT, TT, 0.125f);

    // 4) Wo_t + residual
    gemm_tc<<<dim3(DIM / GBN, RT / GBM), 256>>>(attn, Wo_t, nullptr, xt,
                                                yt, RT, DIM, DIM, FLAG_RES);

    // 5) spatial gather
    gather_s_kernel<<<RS, 128>>>(yt, ys);

    // 6) spatial QKV
    gemm_tc<<<dim3(3 * DIM / GBN, RS / GBM), 256>>>(ys, Wqkv_s, nullptr, nullptr,
                                                    qkv, RS, 3 * DIM, DIM, 0);

    // 7) Linformer K/V projection
    linproj_kernel<<<dim3(FRAMES, DIM / 64, 8), 256>>>(qkv, E, kproj, vproj);

    // 8) spatial attention
    attn_kernel<<<dim3(FRAMES, HEADS), 256, smemS>>>(
        qkv, 3 * DIM, kproj, vproj, DIM, attn, TS, KL, 0.125f);

    // 9) Wo_s + residual
    gemm_tc<<<dim3(DIM / GBN, RS / GBM), 256>>>(attn, Wo_s, nullptr, ys,
                                                ys2, RS, DIM, DIM, FLAG_RES);

    // 10) MLP up + bias + GELU
    gemm_tc<<<dim3(DFF / GBN, RS / GBM), 256>>>(ys2, W1, b1, nullptr,
                                                hbuf, RS, DFF, DIM, FLAG_BIAS | FLAG_GELU);

    // 11) MLP down + bias + residual
    gemm_tc<<<dim3(DIM / GBN, RS / GBM), 256>>>(hbuf, W2, b2, ys2,
                                                out, RS, DIM, DFF, FLAG_BIAS | FLAG_RES);
}

// round 4
// speedup vs baseline: 2.5574x; 1.9475x over previous
#include <cuda_runtime.h>
#include <cuda_bf16.h>
#include <math.h>
#include <stdint.h>

// Problem constants
#define FRAMES  256
#define PATCHES 64
#define DIM     512
#define HEADS   8
#define DH      64
#define DFF     1024
#define KL      128
#define TT      257
#define TS      65
#define RT      (PATCHES * TT)   // 16448
#define RS      (FRAMES * TS)    // 16640

#define FLAG_BIAS 1
#define FLAG_RES  2
#define FLAG_GELU 4

// -------------------- scratch --------------------------------------------
__device__ float g_xt   [RT * DIM];
__device__ float g_qkv  [RS * 3 * DIM];
__device__ float g_attn [RS * DIM];
__device__ float g_yt   [RT * DIM];
__device__ float g_ys   [RS * DIM];
__device__ float g_ys2  [RS * DIM];
__device__ float g_kproj[FRAMES * KL * DIM];
__device__ float g_vproj[FRAMES * KL * DIM];
__device__ float g_h    [RS * DFF];

// -------------------- tf32 helpers ---------------------------------------
__device__ __forceinline__ float f2tf32(float x) {
    uint32_t u;
    asm("cvt.rna.tf32.f32 %0, %1;" : "=r"(u) : "f"(x));
    return __uint_as_float(u);
}

__device__ __forceinline__ void mma_tf32(float (&c)[4], const uint32_t (&a)[4],
                                         const uint32_t (&b)[2]) {
    asm volatile(
        "mma.sync.aligned.m16n8k8.row.col.f32.tf32.tf32.f32 "
        "{%0,%1,%2,%3}, {%4,%5,%6,%7}, {%8,%9}, {%0,%1,%2,%3};"
        : "+f"(c[0]), "+f"(c[1]), "+f"(c[2]), "+f"(c[3])
        : "r"(a[0]), "r"(a[1]), "r"(a[2]), "r"(a[3]), "r"(b[0]), "r"(b[1]));
}

// -------------------- tf32 tensor-core GEMM ------------------------------
#define GBM 64
#define GBN 128
#define GBK 16
#define ASTR (GBM + 4)
#define BSTR (GBN + 4)

__global__ __launch_bounds__(256) void gemm_tc(
    const float* __restrict__ A, const float* __restrict__ B,
    const float* __restrict__ bias, const float* __restrict__ R,
    float* __restrict__ C, int M, int N, int K, int flags)
{
    __shared__ float As[2][GBK][ASTR];
    __shared__ float Bs[2][GBK][BSTR];

    int tid = threadIdx.x;
    int warp = tid >> 5, lane = tid & 31;
    int wr = warp & 1;
    int wc = warp >> 1;
    int r0 = blockIdx.y * GBM;
    int c0 = blockIdx.x * GBN;
    int g  = lane >> 2;
    int tg = lane & 3;

    float acc[2][4][4];
    #pragma unroll
    for (int mt = 0; mt < 2; mt++)
        #pragma unroll
        for (int nt = 0; nt < 4; nt++)
            #pragma unroll
            for (int i = 0; i < 4; i++) acc[mt][nt][i] = 0.0f;

    int arow = tid >> 2;
    int acol = (tid & 3) * 4;
    int br0  = tid >> 5;
    int bc0  = (tid & 31) * 4;

    {
        float4 av = *(const float4*)&A[(size_t)(r0 + arow) * K + acol];
        As[0][acol + 0][arow] = f2tf32(av.x);
        As[0][acol + 1][arow] = f2tf32(av.y);
        As[0][acol + 2][arow] = f2tf32(av.z);
        As[0][acol + 3][arow] = f2tf32(av.w);
        float4 b0 = *(const float4*)&B[(size_t)br0 * N + c0 + bc0];
        float4 b1 = *(const float4*)&B[(size_t)(br0 + 8) * N + c0 + bc0];
        *(float4*)&Bs[0][br0][bc0]     = make_float4(f2tf32(b0.x), f2tf32(b0.y), f2tf32(b0.z), f2tf32(b0.w));
        *(float4*)&Bs[0][br0 + 8][bc0] = make_float4(f2tf32(b1.x), f2tf32(b1.y), f2tf32(b1.z), f2tf32(b1.w));
    }
    __syncthreads();

    int buf = 0;
    for (int k0 = 0; k0 < K; k0 += GBK) {
        if (k0 + GBK < K) {
            int kn = k0 + GBK;
            float4 av = *(const float4*)&A[(size_t)(r0 + arow) * K + kn + acol];
            As[buf ^ 1][acol + 0][arow] = f2tf32(av.x);
            As[buf ^ 1][acol + 1][arow] = f2tf32(av.y);
            As[buf ^ 1][acol + 2][arow] = f2tf32(av.z);
            As[buf ^ 1][acol + 3][arow] = f2tf32(av.w);
            float4 b0 = *(const float4*)&B[(size_t)(kn + br0) * N + c0 + bc0];
            float4 b1 = *(const float4*)&B[(size_t)(kn + br0 + 8) * N + c0 + bc0];
            *(float4*)&Bs[buf ^ 1][br0][bc0]     = make_float4(f2tf32(b0.x), f2tf32(b0.y), f2tf32(b0.z), f2tf32(b0.w));
            *(float4*)&Bs[buf ^ 1][br0 + 8][bc0] = make_float4(f2tf32(b1.x), f2tf32(b1.y), f2tf32(b1.z), f2tf32(b1.w));
        }

        #pragma unroll
        for (int kk = 0; kk < GBK; kk += 8) {
            uint32_t afrag[2][4];
            #pragma unroll
            for (int mt = 0; mt < 2; mt++) {
                int rb = wr * 32 + mt * 16;
                afrag[mt][0] = __float_as_uint(As[buf][kk + tg][rb + g]);
                afrag[mt][1] = __float_as_uint(As[buf][kk + tg][rb + g + 8]);
                afrag[mt][2] = __float_as_uint(As[buf][kk + tg + 4][rb + g]);
                afrag[mt][3] = __float_as_uint(As[buf][kk + tg + 4][rb + g + 8]);
            }
            uint32_t bfrag[4][2];
            #pragma unroll
            for (int nt = 0; nt < 4; nt++) {
                int cb = wc * 32 + nt * 8;
                bfrag[nt][0] = __float_as_uint(Bs[buf][kk + tg][cb + g]);
                bfrag[nt][1] = __float_as_uint(Bs[buf][kk + tg + 4][cb + g]);
            }
            #pragma unroll
            for (int mt = 0; mt < 2; mt++)
                #pragma unroll
                for (int nt = 0; nt < 4; nt++)
                    mma_tf32(acc[mt][nt], afrag[mt], bfrag[nt]);
        }
        __syncthreads();
        buf ^= 1;
    }

    #pragma unroll
    for (int mt = 0; mt < 2; mt++) {
        #pragma unroll
        for (int nt = 0; nt < 4; nt++) {
            int col = c0 + wc * 32 + nt * 8 + 2 * tg;
            #pragma unroll
            for (int half = 0; half < 2; half++) {
                int row = r0 + wr * 32 + mt * 16 + g + half * 8;
                float v0 = acc[mt][nt][half * 2 + 0];
                float v1 = acc[mt][nt][half * 2 + 1];
                if (flags & FLAG_BIAS) { v0 += bias[col]; v1 += bias[col + 1]; }
                if (flags & FLAG_GELU) {
                    v0 = 0.5f * v0 * (1.0f + erff(v0 * 0.70710678118654752f));
                    v1 = 0.5f * v1 * (1.0f + erff(v1 * 0.70710678118654752f));
                }
                if (flags & FLAG_RES) {
                    float2 rr = *(const float2*)&R[(size_t)row * N + col];
                    v0 += rr.x; v1 += rr.y;
                }
                *(float2*)&C[(size_t)row * N + col] = make_float2(v0, v1);
            }
        }
    }
}

// -------------------- tensor-core attention -------------------------------
// One block = one (q-tile of 64 rows, batch, head). Two-pass softmax with the
// full 64 x (ktiles*64) score panel in SMEM. All GEMMs via tf32 mma.
__global__ __launch_bounds__(256) void attn_mma(
    const float* __restrict__ Q, int qStride,
    const float* __restrict__ Kp, const float* __restrict__ Vp, int kvStride,
    float* __restrict__ O, int Tq, int Tk, int ktiles, float scale)
{
    extern __shared__ float sm[];
    const int SST = ktiles * 64 + 4;
    float* Ssm  = sm;                    // 64 * SST score panel
    float* KVs  = sm + 64 * SST;         // 64 x 68 staging tile (Q, then K, then V)
    float* srow = KVs + 64 * 68;         // 64 reciprocal row sums

    int qt = blockIdx.x, b = blockIdx.y, h = blockIdx.z;
    int tid = threadIdx.x, warp = tid >> 5, lane = tid & 31;
    int g = lane >> 2, tg = lane & 3;
    int wm = warp >> 1, wn = warp & 1;   // 4 x 2 warp grid
    int rb = wm * 16;
    int q0 = qt * 64;

    const float* Qb = Q  + (size_t)b * Tq * qStride  + h * DH;
    const float* Kb = Kp + (size_t)b * Tk * kvStride + h * DH;
    const float* Vb = Vp + (size_t)b * Tk * kvStride + h * DH;

    // ---- load Q tile (scaled, tf32) ----
    for (int i = tid; i < 64 * 16; i += 256) {
        int r = i >> 4, c4 = (i & 15) * 4;
        int rq = q0 + r; if (rq > Tq - 1) rq = Tq - 1;
        float4 v = *(const float4*)&Qb[(size_t)rq * qStride + c4];
        *(float4*)&KVs[r * 68 + c4] = make_float4(
            f2tf32(v.x * scale), f2tf32(v.y * scale),
            f2tf32(v.z * scale), f2tf32(v.w * scale));
    }
    __syncthreads();

    // Q fragments in registers for all 8 k-steps
    uint32_t aq[8][4];
    #pragma unroll
    for (int ks = 0; ks < 8; ks++) {
        aq[ks][0] = __float_as_uint(KVs[(rb + g)     * 68 + ks * 8 + tg]);
        aq[ks][1] = __float_as_uint(KVs[(rb + g + 8) * 68 + ks * 8 + tg]);
        aq[ks][2] = __float_as_uint(KVs[(rb + g)     * 68 + ks * 8 + tg + 4]);
        aq[ks][3] = __float_as_uint(KVs[(rb + g + 8) * 68 + ks * 8 + tg + 4]);
    }

    // ---- phase 1: S = Q K^T, tile by tile ----
    for (int kt = 0; kt < ktiles; kt++) {
        __syncthreads();   // protect KVs (Q frags extracted / previous K reads done)
        for (int i = tid; i < 64 * 16; i += 256) {
            int r = i >> 4, c4 = (i & 15) * 4;
            int rk = kt * 64 + r; if (rk > Tk - 1) rk = Tk - 1;
            float4 v = *(const float4*)&Kb[(size_t)rk * kvStride + c4];
            *(float4*)&KVs[r * 68 + c4] = make_float4(
                f2tf32(v.x), f2tf32(v.y), f2tf32(v.z), f2tf32(v.w));
        }
        __syncthreads();

        float cS[4][4];
        #pragma unroll
        for (int nt = 0; nt < 4; nt++)
            #pragma unroll
            for (int i = 0; i < 4; i++) cS[nt][i] = 0.0f;

        #pragma unroll
        for (int ks = 0; ks < 8; ks++) {
            uint32_t bf[4][2];
            #pragma unroll
            for (int nt = 0; nt < 4; nt++) {
                int n0 = wn * 32 + nt * 8;
                bf[nt][0] = __float_as_uint(KVs[(n0 + g) * 68 + ks * 8 + tg]);
                bf[nt][1] = __float_as_uint(KVs[(n0 + g) * 68 + ks * 8 + tg + 4]);
            }
            #pragma unroll
            for (int nt = 0; nt < 4; nt++)
                mma_tf32(cS[nt], aq[ks], bf[nt]);
        }

        // store (with key mask) into score panel
        #pragma unroll
        for (int nt = 0; nt < 4; nt++) {
            int cl = wn * 32 + nt * 8 + 2 * tg;
            int cg = kt * 64 + cl;
            bool ok0 = cg < Tk, ok1 = cg + 1 < Tk;
            *(float2*)&Ssm[(rb + g) * SST + kt * 64 + cl] =
                make_float2(ok0 ? cS[nt][0] : -1e30f, ok1 ? cS[nt][1] : -1e30f);
            *(float2*)&Ssm[(rb + g + 8) * SST + kt * 64 + cl] =
                make_float2(ok0 ? cS[nt][2] : -1e30f, ok1 ? cS[nt][3] : -1e30f);
        }
    }
    __syncthreads();

    // ---- phase 2: softmax (4 lanes per row, conflict-free scalar) ----
    {
        int row = tid >> 2, sub = tid & 3;
        float* Sr = &Ssm[row * SST];
        int nc = ktiles * 64;
        float m = -1e30f;
        for (int c = sub; c < nc; c += 4) m = fmaxf(m, Sr[c]);
        m = fmaxf(m, __shfl_xor_sync(0xffffffffu, m, 1));
        m = fmaxf(m, __shfl_xor_sync(0xffffffffu, m, 2));
        float s = 0.0f;
        for (int c = sub; c < nc; c += 4) {
            float e = __expf(Sr[c] - m);
            s += e;
            Sr[c] = f2tf32(e);
        }
        s += __shfl_xor_sync(0xffffffffu, s, 1);
        s += __shfl_xor_sync(0xffffffffu, s, 2);
        if (sub == 0) srow[row] = 1.0f / s;
    }
    __syncthreads();

    float inv0 = srow[rb + g], inv1 = srow[rb + g + 8];

    // ---- phase 3: O = P V ----
    float cO[4][4];
    #pragma unroll
    for (int nt = 0; nt < 4; nt++)
        #pragma unroll
        for (int i = 0; i < 4; i++) cO[nt][i] = 0.0f;

    for (int kt = 0; kt < ktiles; kt++) {
        __syncthreads();
        for (int i = tid; i < 64 * 16; i += 256) {
            int r = i >> 4, c4 = (i & 15) * 4;
            int rk = kt * 64 + r; if (rk > Tk - 1) rk = Tk - 1;
            float4 v = *(const float4*)&Vb[(size_t)rk * kvStride + c4];
            *(float4*)&KVs[r * 68 + c4] = make_float4(
                f2tf32(v.x), f2tf32(v.y), f2tf32(v.z), f2tf32(v.w));
        }
        __syncthreads();

        #pragma unroll
        for (int ks = 0; ks < 8; ks++) {
            uint32_t ap[4];
            int kb = kt * 64 + ks * 8;
            ap[0] = __float_as_uint(Ssm[(rb + g)     * SST + kb + tg]);
            ap[1] = __float_as_uint(Ssm[(rb + g + 8) * SST + kb + tg]);
            ap[2] = __float_as_uint(Ssm[(rb + g)     * SST + kb + tg + 4]);
            ap[3] = __float_as_uint(Ssm[(rb + g + 8) * SST + kb + tg + 4]);
            #pragma unroll
            for (int nt = 0; nt < 4; nt++) {
                int n0 = wn * 32 + nt * 8;
                uint32_t bv[2];
                bv[0] = __float_as_uint(KVs[(ks * 8 + tg)     * 68 + n0 + g]);
                bv[1] = __float_as_uint(KVs[(ks * 8 + tg + 4) * 68 + n0 + g]);
                mma_tf32(cO[nt], ap, bv);
            }
        }
    }

    // ---- epilogue: normalize + store ----
    #pragma unroll
    for (int nt = 0; nt < 4; nt++) {
        int dl = wn * 32 + nt * 8 + 2 * tg;
        int r0g = q0 + rb + g;
        if (r0g < Tq)
            *(float2*)&O[((size_t)b * Tq + r0g) * DIM + h * DH + dl] =
                make_float2(cO[nt][0] * inv0, cO[nt][1] * inv0);
        int r1g = q0 + rb + g + 8;
        if (r1g < Tq)
            *(float2*)&O[((size_t)b * Tq + r1g) * DIM + h * DH + dl] =
                make_float2(cO[nt][2] * inv1, cO[nt][3] * inv1);
    }
}

// -------------------- Linformer K/V projection ----------------------------
__global__ __launch_bounds__(256) void linproj_kernel(
    const float* __restrict__ qkv, const float* __restrict__ E,
    float* __restrict__ kproj, float* __restrict__ vproj)
{
    __shared__ float Es[TS * 32];
    __shared__ float Ksm[TS * 64];

    int b = blockIdx.x;
    int c0 = blockIdx.y * 64;
    int zz = blockIdx.z;
    int kvsel = zz & 1;
    int kkt = zz >> 1;
    int tid = threadIdx.x;

    int colbase = DIM + kvsel * DIM + c0;
    for (int i = tid; i < TS * 64; i += 256) {
        int j = i >> 6, c = i & 63;
        Ksm[i] = qkv[((size_t)b * TS + j) * (3 * DIM) + colbase + c];
    }
    for (int i = tid; i < TS * 32; i += 256) {
        int j = i >> 5, q = i & 31;
        Es[i] = E[j * KL + kkt * 32 + q];
    }
    __syncthreads();

    int c = tid & 63, kg = tid >> 6;
    float acc[8];
    #pragma unroll
    for (int i = 0; i < 8; i++) acc[i] = 0.0f;

    for (int j = 0; j < TS; j++) {
        float kv = Ksm[j * 64 + c];
        #pragma unroll
        for (int i = 0; i < 8; i++)
            acc[i] += kv * Es[j * 32 + kg * 8 + i];
    }

    float* dst = kvsel ? vproj : kproj;
    #pragma unroll
    for (int i = 0; i < 8; i++) {
        int kk = kkt * 32 + kg * 8 + i;
        dst[((size_t)b * KL + kk) * DIM + c0 + c] = acc[i];
    }
}

// -------------------- token rearrangement ---------------------------------
__global__ void gather_t_kernel(const float* __restrict__ x, float* __restrict__ xt)
{
    int row = blockIdx.x;
    int p = row / TT, t = row % TT;
    const float4* s = (const float4*)(t == 0 ? x
                        : x + (size_t)(1 + (t - 1) * PATCHES + p) * DIM);
    float4* d = (float4*)(xt + (size_t)row * DIM);
    d[threadIdx.x] = s[threadIdx.x];
}

__global__ void gather_s_kernel(const float* __restrict__ yt, float* __restrict__ ys)
{
    int row = blockIdx.x;
    int f = row / TS, t = row % TS;
    const float* src = (t == 0)
        ? yt + (size_t)((f & 63) * TT) * DIM
        : yt + (size_t)((t - 1) * TT + 1 + f) * DIM;
    ((float4*)(ys + (size_t)row * DIM))[threadIdx.x] = ((const float4*)src)[threadIdx.x];
}

// -------------------- launch ----------------------------------------------
extern "C" void kernel_launch(void* const* d_in, const int* in_sizes, int n_in,
                              void* d_out, int out_size)
{
    const float* x      = (const float*)d_in[0];
    const float* Wqkv_t = (const float*)d_in[1];
    const float* Wo_t   = (const float*)d_in[2];
    const float* Wqkv_s = (const float*)d_in[3];
    const float* Wo_s   = (const float*)d_in[4];
    const float* E      = (const float*)d_in[5];
    const float* W1     = (const float*)d_in[6];
    const float* b1     = (const float*)d_in[7];
    const float* W2     = (const float*)d_in[8];
    const float* b2     = (const float*)d_in[9];
    float* out = (float*)d_out;

    float *xt, *qkv, *attn, *yt, *ys, *ys2, *kproj, *vproj, *hbuf;
    cudaGetSymbolAddress((void**)&xt,    g_xt);
    cudaGetSymbolAddress((void**)&qkv,   g_qkv);
    cudaGetSymbolAddress((void**)&attn,  g_attn);
    cudaGetSymbolAddress((void**)&yt,    g_yt);
    cudaGetSymbolAddress((void**)&ys,    g_ys);
    cudaGetSymbolAddress((void**)&ys2,   g_ys2);
    cudaGetSymbolAddress((void**)&kproj, g_kproj);
    cudaGetSymbolAddress((void**)&vproj, g_vproj);
    cudaGetSymbolAddress((void**)&hbuf,  g_h);

    // attention smem: temporal ktiles=5 -> 64*324 + 64*68 + 64 floats = 100,608 B
    const int ktT = (TT + 63) / 64;          // 5
    const int ktS = (KL + 63) / 64;          // 2
    const int smemT = (64 * (ktT * 64 + 4) + 64 * 68 + 64) * (int)sizeof(float);
    const int smemS = (64 * (ktS * 64 + 4) + 64 * 68 + 64) * (int)sizeof(float);
    cudaFuncSetAttribute(attn_mma, cudaFuncAttributeMaxDynamicSharedMemorySize, smemT);

    // 1) temporal token gather
    gather_t_kernel<<<RT, 128>>>(x, xt);

    // 2) temporal QKV
    gemm_tc<<<dim3(3 * DIM / GBN, RT / GBM), 256>>>(xt, Wqkv_t, nullptr, nullptr,
                                                    qkv, RT, 3 * DIM, DIM, 0);

    // 3) temporal attention (Tq=Tk=257)
    attn_mma<<<dim3((TT + 63) / 64, PATCHES, HEADS), 256, smemT>>>(
        qkv, 3 * DIM, qkv + DIM, qkv + 2 * DIM, 3 * DIM, attn, TT, TT, ktT, 0.125f);

    // 4) Wo_t + residual
    gemm_tc<<<dim3(DIM / GBN, RT / GBM), 256>>>(attn, Wo_t, nullptr, xt,
                                                yt, RT, DIM, DIM, FLAG_RES);

    // 5) spatial gather
    gather_s_kernel<<<RS, 128>>>(yt, ys);

    // 6) spatial QKV
    gemm_tc<<<dim3(3 * DIM / GBN, RS / GBM), 256>>>(ys, Wqkv_s, nullptr, nullptr,
                                                    qkv, RS, 3 * DIM, DIM, 0);

    // 7) Linformer K/V projection
    linproj_kernel<<<dim3(FRAMES, DIM / 64, 8), 256>>>(qkv, E, kproj, vproj);

    // 8) spatial attention (Tq=65, Tk=128)
    attn_mma<<<dim3((TS + 63) / 64, FRAMES, HEADS), 256, smemS>>>(
        qkv, 3 * DIM, kproj, vproj, DIM, attn, TS, KL, ktS, 0.125f);

    // 9) Wo_s + residual
    gemm_tc<<<dim3(DIM / GBN, RS / GBM), 256>>>(attn, Wo_s, nullptr, ys,
                                                ys2, RS, DIM, DIM, FLAG_RES);

    // 10) MLP up + bias + GELU
    gemm_tc<<<dim3(DFF / GBN, RS / GBM), 256>>>(ys2, W1, b1, nullptr,
                                                hbuf, RS, DFF, DIM, FLAG_BIAS | FLAG_GELU);

    // 11) MLP down + bias + residual
    gemm_tc<<<dim3(DIM / GBN, RS / GBM), 256>>>(hbuf, W2, b2, ys2,
                                                out, RS, DIM, DFF, FLAG_BIAS | FLAG_RES);
}

// round 10
// speedup vs baseline: 3.0653x; 1.1986x over previous
#include <cuda_runtime.h>
#include <cuda_bf16.h>
#include <cuda_fp16.h>
#include <math.h>
#include <stdint.h>

// Problem constants
#define FRAMES  256
#define PATCHES 64
#define DIM     512
#define HEADS   8
#define DH      64
#define DFF     1024
#define KL      128
#define TT      257
#define TS      65
#define RT      (PATCHES * TT)   // 16448
#define RS      (FRAMES * TS)    // 16640

#define FLAG_BIAS 1
#define FLAG_RES  2
#define FLAG_GELU 4

// -------------------- scratch --------------------------------------------
__device__ float g_xt   [RT * DIM];
__device__ float g_qkv  [RS * 3 * DIM];
__device__ float g_attn [RS * DIM];
__device__ float g_yt   [RT * DIM];
__device__ float g_ys   [RS * DIM];
__device__ float g_ys2  [RS * DIM];
__device__ float g_kproj[FRAMES * KL * DIM];
__device__ float g_vproj[FRAMES * KL * DIM];
__device__ float g_h    [RS * DFF];

// -------------------- mma helpers ----------------------------------------
__device__ __forceinline__ float f2tf32(float x) {
    uint32_t u;
    asm("cvt.rna.tf32.f32 %0, %1;" : "=r"(u) : "f"(x));
    return __uint_as_float(u);
}

__device__ __forceinline__ void mma_tf32(float (&c)[4], const uint32_t (&a)[4],
                                         const uint32_t (&b)[2]) {
    asm volatile(
        "mma.sync.aligned.m16n8k8.row.col.f32.tf32.tf32.f32 "
        "{%0,%1,%2,%3}, {%4,%5,%6,%7}, {%8,%9}, {%0,%1,%2,%3};"
        : "+f"(c[0]), "+f"(c[1]), "+f"(c[2]), "+f"(c[3])
        : "r"(a[0]), "r"(a[1]), "r"(a[2]), "r"(a[3]), "r"(b[0]), "r"(b[1]));
}

__device__ __forceinline__ void mma_f16(float (&c)[4], const uint32_t (&a)[4],
                                        uint32_t b0, uint32_t b1) {
    asm volatile(
        "mma.sync.aligned.m16n8k16.row.col.f32.f16.f16.f32 "
        "{%0,%1,%2,%3}, {%4,%5,%6,%7}, {%8,%9}, {%0,%1,%2,%3};"
        : "+f"(c[0]), "+f"(c[1]), "+f"(c[2]), "+f"(c[3])
        : "r"(a[0]), "r"(a[1]), "r"(a[2]), "r"(a[3]), "r"(b0), "r"(b1));
}

__device__ __forceinline__ void ldsm4(uint32_t (&r)[4], uint32_t addr) {
    asm volatile("ldmatrix.sync.aligned.m8n8.x4.shared.b16 {%0,%1,%2,%3}, [%4];"
        : "=r"(r[0]), "=r"(r[1]), "=r"(r[2]), "=r"(r[3]) : "r"(addr));
}
__device__ __forceinline__ void ldsm4t(uint32_t (&r)[4], uint32_t addr) {
    asm volatile("ldmatrix.sync.aligned.m8n8.x4.trans.shared.b16 {%0,%1,%2,%3}, [%4];"
        : "=r"(r[0]), "=r"(r[1]), "=r"(r[2]), "=r"(r[3]) : "r"(addr));
}

__device__ __forceinline__ uint32_t h2u(__half2 h) { return *(uint32_t*)&h; }

// -------------------- fp16 tensor-core GEMM -------------------------------
// C[M,N] = A[M,K] @ B[K,N] (+bias)(+gelu)(+res). M%64==0, N%128==0, K%32==0.
// Block tile 64x128x32, double-buffered, fragments via ldmatrix.
#define HAS 40    // A smem row stride (halves): 80B = 5x16B (odd -> no conflicts)
#define HBS 136   // B smem row stride (halves): 272B = 17x16B (odd)
#define ASZ (64 * HAS)   // halves per A buffer
#define BSZ (32 * HBS)   // halves per B buffer

__device__ __forceinline__ void stage_ab(
    const float* __restrict__ A, const float* __restrict__ B,
    __half* As, __half* Bs, int r0, int c0, int K, int N, int k0, int tid)
{
    // A: 64 rows x 32 cols -> thread t: row t>>2, 8 cols at (t&3)*8
    int r = tid >> 2, ca = (tid & 3) * 8;
    const float4* sa = (const float4*)&A[(size_t)(r0 + r) * K + k0 + ca];
    float4 f0 = sa[0], f1 = sa[1];
    uint4 ua = make_uint4(
        h2u(__floats2half2_rn(f0.x, f0.y)), h2u(__floats2half2_rn(f0.z, f0.w)),
        h2u(__floats2half2_rn(f1.x, f1.y)), h2u(__floats2half2_rn(f1.z, f1.w)));
    *(uint4*)&As[r * HAS + ca] = ua;

    // B: 32 rows x 128 cols -> thread t: row t>>3, 16 cols at (t&7)*16
    int k = tid >> 3, cb = (tid & 7) * 16;
    const float4* sb = (const float4*)&B[(size_t)(k0 + k) * N + c0 + cb];
    float4 g0 = sb[0], g1 = sb[1], g2 = sb[2], g3 = sb[3];
    *(uint4*)&Bs[k * HBS + cb] = make_uint4(
        h2u(__floats2half2_rn(g0.x, g0.y)), h2u(__floats2half2_rn(g0.z, g0.w)),
        h2u(__floats2half2_rn(g1.x, g1.y)), h2u(__floats2half2_rn(g1.z, g1.w)));
    *(uint4*)&Bs[k * HBS + cb + 8] = make_uint4(
        h2u(__floats2half2_rn(g2.x, g2.y)), h2u(__floats2half2_rn(g2.z, g2.w)),
        h2u(__floats2half2_rn(g3.x, g3.y)), h2u(__floats2half2_rn(g3.z, g3.w)));
}

__global__ __launch_bounds__(256) void gemm_f16(
    const float* __restrict__ A, const float* __restrict__ B,
    const float* __restrict__ bias, const float* __restrict__ R,
    float* __restrict__ C, int M, int N, int K, int flags)
{
    __shared__ __align__(16) __half As[2][ASZ];
    __shared__ __align__(16) __half Bs[2][BSZ];

    int tid = threadIdx.x;
    int warp = tid >> 5, lane = tid & 31;
    int wr = warp & 1;            // 2 warp-rows x 32
    int wc = warp >> 1;           // 4 warp-cols x 32
    int r0 = blockIdx.y * 64;
    int c0 = blockIdx.x * 128;
    int g = lane >> 2, tg = lane & 3;

    float acc[2][4][4];
    #pragma unroll
    for (int mt = 0; mt < 2; mt++)
        #pragma unroll
        for (int nt = 0; nt < 4; nt++)
            #pragma unroll
            for (int i = 0; i < 4; i++) acc[mt][nt][i] = 0.0f;

    stage_ab(A, B, As[0], Bs[0], r0, c0, K, N, 0, tid);
    __syncthreads();

    // ldmatrix per-lane base addresses (bytes in shared space)
    int l15 = lane & 15, lhi = lane >> 4;
    uint32_t aAddr = (uint32_t)__cvta_generic_to_shared(&As[0][0])
                   + (uint32_t)(((wr * 32 + l15) * HAS + lhi * 8) * 2);
    int bq = (lane & 7) + ((lane >> 3) & 1) * 8;
    uint32_t bAddr = (uint32_t)__cvta_generic_to_shared(&Bs[0][0])
                   + (uint32_t)((bq * HBS + wc * 32 + lhi * 8) * 2);

    int buf = 0;
    for (int k0 = 0; k0 < K; k0 += 32) {
        if (k0 + 32 < K)
            stage_ab(A, B, As[buf ^ 1], Bs[buf ^ 1], r0, c0, K, N, k0 + 32, tid);

        uint32_t aB = aAddr + buf * (ASZ * 2);
        uint32_t bB = bAddr + buf * (BSZ * 2);
        #pragma unroll
        for (int kk = 0; kk < 32; kk += 16) {
            uint32_t a[2][4], b[2][4];
            ldsm4 (a[0], aB + kk * 2);
            ldsm4 (a[1], aB + kk * 2 + 16 * HAS * 2);
            ldsm4t(b[0], bB + kk * HBS * 2);
            ldsm4t(b[1], bB + kk * HBS * 2 + 16 * 2);
            #pragma unroll
            for (int mt = 0; mt < 2; mt++)
                #pragma unroll
                for (int nt = 0; nt < 4; nt++)
                    mma_f16(acc[mt][nt], a[mt],
                            b[nt >> 1][(nt & 1) * 2], b[nt >> 1][(nt & 1) * 2 + 1]);
        }
        __syncthreads();
        buf ^= 1;
    }

    // epilogue (fp32)
    #pragma unroll
    for (int mt = 0; mt < 2; mt++) {
        #pragma unroll
        for (int nt = 0; nt < 4; nt++) {
            int col = c0 + wc * 32 + nt * 8 + 2 * tg;
            #pragma unroll
            for (int half = 0; half < 2; half++) {
                int row = r0 + wr * 32 + mt * 16 + g + half * 8;
                float v0 = acc[mt][nt][half * 2 + 0];
                float v1 = acc[mt][nt][half * 2 + 1];
                if (flags & FLAG_BIAS) { v0 += bias[col]; v1 += bias[col + 1]; }
                if (flags & FLAG_GELU) {
                    v0 = 0.5f * v0 * (1.0f + erff(v0 * 0.70710678118654752f));
                    v1 = 0.5f * v1 * (1.0f + erff(v1 * 0.70710678118654752f));
                }
                if (flags & FLAG_RES) {
                    float2 rr = *(const float2*)&R[(size_t)row * N + col];
                    v0 += rr.x; v1 += rr.y;
                }
                *(float2*)&C[(size_t)row * N + col] = make_float2(v0, v1);
            }
        }
    }
}

// -------------------- tensor-core attention (tf32, verified) --------------
__global__ __launch_bounds__(256) void attn_mma(
    const float* __restrict__ Q, int qStride,
    const float* __restrict__ Kp, const float* __restrict__ Vp, int kvStride,
    float* __restrict__ O, int Tq, int Tk, int ktiles, float scale)
{
    extern __shared__ float sm[];
    const int SST = ktiles * 64 + 4;
    float* Ssm  = sm;
    float* KVs  = sm + 64 * SST;
    float* srow = KVs + 64 * 68;

    int qt = blockIdx.x, b = blockIdx.y, h = blockIdx.z;
    int tid = threadIdx.x, warp = tid >> 5, lane = tid & 31;
    int g = lane >> 2, tg = lane & 3;
    int wm = warp >> 1, wn = warp & 1;
    int rb = wm * 16;
    int q0 = qt * 64;

    const float* Qb = Q  + (size_t)b * Tq * qStride  + h * DH;
    const float* Kb = Kp + (size_t)b * Tk * kvStride + h * DH;
    const float* Vb = Vp + (size_t)b * Tk * kvStride + h * DH;

    for (int i = tid; i < 64 * 16; i += 256) {
        int r = i >> 4, c4 = (i & 15) * 4;
        int rq = q0 + r; if (rq > Tq - 1) rq = Tq - 1;
        float4 v = *(const float4*)&Qb[(size_t)rq * qStride + c4];
        *(float4*)&KVs[r * 68 + c4] = make_float4(
            f2tf32(v.x * scale), f2tf32(v.y * scale),
            f2tf32(v.z * scale), f2tf32(v.w * scale));
    }
    __syncthreads();

    uint32_t aq[8][4];
    #pragma unroll
    for (int ks = 0; ks < 8; ks++) {
        aq[ks][0] = __float_as_uint(KVs[(rb + g)     * 68 + ks * 8 + tg]);
        aq[ks][1] = __float_as_uint(KVs[(rb + g + 8) * 68 + ks * 8 + tg]);
        aq[ks][2] = __float_as_uint(KVs[(rb + g)     * 68 + ks * 8 + tg + 4]);
        aq[ks][3] = __float_as_uint(KVs[(rb + g + 8) * 68 + ks * 8 + tg + 4]);
    }

    for (int kt = 0; kt < ktiles; kt++) {
        __syncthreads();
        for (int i = tid; i < 64 * 16; i += 256) {
            int r = i >> 4, c4 = (i & 15) * 4;
            int rk = kt * 64 + r; if (rk > Tk - 1) rk = Tk - 1;
            float4 v = *(const float4*)&Kb[(size_t)rk * kvStride + c4];
            *(float4*)&KVs[r * 68 + c4] = make_float4(
                f2tf32(v.x), f2tf32(v.y), f2tf32(v.z), f2tf32(v.w));
        }
        __syncthreads();

        float cS[4][4];
        #pragma unroll
        for (int nt = 0; nt < 4; nt++)
            #pragma unroll
            for (int i = 0; i < 4; i++) cS[nt][i] = 0.0f;

        #pragma unroll
        for (int ks = 0; ks < 8; ks++) {
            uint32_t bf[4][2];
            #pragma unroll
            for (int nt = 0; nt < 4; nt++) {
                int n0 = wn * 32 + nt * 8;
                bf[nt][0] = __float_as_uint(KVs[(n0 + g) * 68 + ks * 8 + tg]);
                bf[nt][1] = __float_as_uint(KVs[(n0 + g) * 68 + ks * 8 + tg + 4]);
            }
            #pragma unroll
            for (int nt = 0; nt < 4; nt++)
                mma_tf32(cS[nt], aq[ks], bf[nt]);
        }

        #pragma unroll
        for (int nt = 0; nt < 4; nt++) {
            int cl = wn * 32 + nt * 8 + 2 * tg;
            int cg = kt * 64 + cl;
            bool ok0 = cg < Tk, ok1 = cg + 1 < Tk;
            *(float2*)&Ssm[(rb + g) * SST + kt * 64 + cl] =
                make_float2(ok0 ? cS[nt][0] : -1e30f, ok1 ? cS[nt][1] : -1e30f);
            *(float2*)&Ssm[(rb + g + 8) * SST + kt * 64 + cl] =
                make_float2(ok0 ? cS[nt][2] : -1e30f, ok1 ? cS[nt][3] : -1e30f);
        }
    }
    __syncthreads();

    {
        int row = tid >> 2, sub = tid & 3;
        float* Sr = &Ssm[row * SST];
        int nc = ktiles * 64;
        float m = -1e30f;
        for (int c = sub; c < nc; c += 4) m = fmaxf(m, Sr[c]);
        m = fmaxf(m, __shfl_xor_sync(0xffffffffu, m, 1));
        m = fmaxf(m, __shfl_xor_sync(0xffffffffu, m, 2));
        float s = 0.0f;
        for (int c = sub; c < nc; c += 4) {
            float e = __expf(Sr[c] - m);
            s += e;
            Sr[c] = f2tf32(e);
        }
        s += __shfl_xor_sync(0xffffffffu, s, 1);
        s += __shfl_xor_sync(0xffffffffu, s, 2);
        if (sub == 0) srow[row] = 1.0f / s;
    }
    __syncthreads();

    float inv0 = srow[rb + g], inv1 = srow[rb + g + 8];

    float cO[4][4];
    #pragma unroll
    for (int nt = 0; nt < 4; nt++)
        #pragma unroll
        for (int i = 0; i < 4; i++) cO[nt][i] = 0.0f;

    for (int kt = 0; kt < ktiles; kt++) {
        __syncthreads();
        for (int i = tid; i < 64 * 16; i += 256) {
            int r = i >> 4, c4 = (i & 15) * 4;
            int rk = kt * 64 + r; if (rk > Tk - 1) rk = Tk - 1;
            float4 v = *(const float4*)&Vb[(size_t)rk * kvStride + c4];
            *(float4*)&KVs[r * 68 + c4] = make_float4(
                f2tf32(v.x), f2tf32(v.y), f2tf32(v.z), f2tf32(v.w));
        }
        __syncthreads();

        #pragma unroll
        for (int ks = 0; ks < 8; ks++) {
            uint32_t ap[4];
            int kb = kt * 64 + ks * 8;
            ap[0] = __float_as_uint(Ssm[(rb + g)     * SST + kb + tg]);
            ap[1] = __float_as_uint(Ssm[(rb + g + 8) * SST + kb + tg]);
            ap[2] = __float_as_uint(Ssm[(rb + g)     * SST + kb + tg + 4]);
            ap[3] = __float_as_uint(Ssm[(rb + g + 8) * SST + kb + tg + 4]);
            #pragma unroll
            for (int nt = 0; nt < 4; nt++) {
                int n0 = wn * 32 + nt * 8;
                uint32_t bv[2];
                bv[0] = __float_as_uint(KVs[(ks * 8 + tg)     * 68 + n0 + g]);
                bv[1] = __float_as_uint(KVs[(ks * 8 + tg + 4) * 68 + n0 + g]);
                mma_tf32(cO[nt], ap, bv);
            }
        }
    }

    #pragma unroll
    for (int nt = 0; nt < 4; nt++) {
        int dl = wn * 32 + nt * 8 + 2 * tg;
        int r0g = q0 + rb + g;
        if (r0g < Tq)
            *(float2*)&O[((size_t)b * Tq + r0g) * DIM + h * DH + dl] =
                make_float2(cO[nt][0] * inv0, cO[nt][1] * inv0);
        int r1g = q0 + rb + g + 8;
        if (r1g < Tq)
            *(float2*)&O[((size_t)b * Tq + r1g) * DIM + h * DH + dl] =
                make_float2(cO[nt][2] * inv1, cO[nt][3] * inv1);
    }
}

// -------------------- Linformer K/V projection ----------------------------
__global__ __launch_bounds__(256) void linproj_kernel(
    const float* __restrict__ qkv, const float* __restrict__ E,
    float* __restrict__ kproj, float* __restrict__ vproj)
{
    __shared__ float Es[TS * 32];
    __shared__ float Ksm[TS * 64];

    int b = blockIdx.x;
    int c0 = blockIdx.y * 64;
    int zz = blockIdx.z;
    int kvsel = zz & 1;
    int kkt = zz >> 1;
    int tid = threadIdx.x;

    int colbase = DIM + kvsel * DIM + c0;
    for (int i = tid; i < TS * 64; i += 256) {
        int j = i >> 6, c = i & 63;
        Ksm[i] = qkv[((size_t)b * TS + j) * (3 * DIM) + colbase + c];
    }
    for (int i = tid; i < TS * 32; i += 256) {
        int j = i >> 5, q = i & 31;
        Es[i] = E[j * KL + kkt * 32 + q];
    }
    __syncthreads();

    int c = tid & 63, kg = tid >> 6;
    float acc[8];
    #pragma unroll
    for (int i = 0; i < 8; i++) acc[i] = 0.0f;

    for (int j = 0; j < TS; j++) {
        float kv = Ksm[j * 64 + c];
        #pragma unroll
        for (int i = 0; i < 8; i++)
            acc[i] += kv * Es[j * 32 + kg * 8 + i];
    }

    float* dst = kvsel ? vproj : kproj;
    #pragma unroll
    for (int i = 0; i < 8; i++) {
        int kk = kkt * 32 + kg * 8 + i;
        dst[((size_t)b * KL + kk) * DIM + c0 + c] = acc[i];
    }
}

// -------------------- token rearrangement ---------------------------------
__global__ void gather_t_kernel(const float* __restrict__ x, float* __restrict__ xt)
{
    int row = blockIdx.x;
    int p = row / TT, t = row % TT;
    const float4* s = (const float4*)(t == 0 ? x
                        : x + (size_t)(1 + (t - 1) * PATCHES + p) * DIM);
    float4* d = (float4*)(xt + (size_t)row * DIM);
    d[threadIdx.x] = s[threadIdx.x];
}

__global__ void gather_s_kernel(const float* __restrict__ yt, float* __restrict__ ys)
{
    int row = blockIdx.x;
    int f = row / TS, t = row % TS;
    const float* src = (t == 0)
        ? yt + (size_t)((f & 63) * TT) * DIM
        : yt + (size_t)((t - 1) * TT + 1 + f) * DIM;
    ((float4*)(ys + (size_t)row * DIM))[threadIdx.x] = ((const float4*)src)[threadIdx.x];
}

// -------------------- launch ----------------------------------------------
extern "C" void kernel_launch(void* const* d_in, const int* in_sizes, int n_in,
                              void* d_out, int out_size)
{
    const float* x      = (const float*)d_in[0];
    const float* Wqkv_t = (const float*)d_in[1];
    const float* Wo_t   = (const float*)d_in[2];
    const float* Wqkv_s = (const float*)d_in[3];
    const float* Wo_s   = (const float*)d_in[4];
    const float* E      = (const float*)d_in[5];
    const float* W1     = (const float*)d_in[6];
    const float* b1     = (const float*)d_in[7];
    const float* W2     = (const float*)d_in[8];
    const float* b2     = (const float*)d_in[9];
    float* out = (float*)d_out;

    float *xt, *qkv, *attn, *yt, *ys, *ys2, *kproj, *vproj, *hbuf;
    cudaGetSymbolAddress((void**)&xt,    g_xt);
    cudaGetSymbolAddress((void**)&qkv,   g_qkv);
    cudaGetSymbolAddress((void**)&attn,  g_attn);
    cudaGetSymbolAddress((void**)&yt,    g_yt);
    cudaGetSymbolAddress((void**)&ys,    g_ys);
    cudaGetSymbolAddress((void**)&ys2,   g_ys2);
    cudaGetSymbolAddress((void**)&kproj, g_kproj);
    cudaGetSymbolAddress((void**)&vproj, g_vproj);
    cudaGetSymbolAddress((void**)&hbuf,  g_h);

    const int ktT = (TT + 63) / 64;          // 5 key tiles (temporal)
    const int ktS = (KL + 63) / 64;          // 2 key tiles (spatial)
    const int qtT = (TT + 63) / 64;          // 5 query tiles (temporal)
    const int qtS = (TS + 63) / 64;          // 2 query tiles (spatial)  << the fix
    const int smemT = (64 * (ktT * 64 + 4) + 64 * 68 + 64) * (int)sizeof(float);
    const int smemS = (64 * (ktS * 64 + 4) + 64 * 68 + 64) * (int)sizeof(float);
    cudaFuncSetAttribute(attn_mma, cudaFuncAttributeMaxDynamicSharedMemorySize, smemT);

    // 1) temporal token gather
    gather_t_kernel<<<RT, 128>>>(x, xt);

    // 2) temporal QKV
    gemm_f16<<<dim3(3 * DIM / 128, RT / 64), 256>>>(xt, Wqkv_t, nullptr, nullptr,
                                                    qkv, RT, 3 * DIM, DIM, 0);

    // 3) temporal attention (Tq=Tk=257)
    attn_mma<<<dim3(qtT, PATCHES, HEADS), 256, smemT>>>(
        qkv, 3 * DIM, qkv + DIM, qkv + 2 * DIM, 3 * DIM, attn, TT, TT, ktT, 0.125f);

    // 4) Wo_t + residual
    gemm_f16<<<dim3(DIM / 128, RT / 64), 256>>>(attn, Wo_t, nullptr, xt,
                                                yt, RT, DIM, DIM, FLAG_RES);

    // 5) spatial gather
    gather_s_kernel<<<RS, 128>>>(yt, ys);

    // 6) spatial QKV
    gemm_f16<<<dim3(3 * DIM / 128, RS / 64), 256>>>(ys, Wqkv_s, nullptr, nullptr,
                                                    qkv, RS, 3 * DIM, DIM, 0);

    // 7) Linformer K/V projection
    linproj_kernel<<<dim3(FRAMES, DIM / 64, 8), 256>>>(qkv, E, kproj, vproj);

    // 8) spatial attention (Tq=65 -> TWO query tiles; Tk=128)
    attn_mma<<<dim3(qtS, FRAMES, HEADS), 256, smemS>>>(
        qkv, 3 * DIM, kproj, vproj, DIM, attn, TS, KL, ktS, 0.125f);

    // 9) Wo_s + residual
    gemm_f16<<<dim3(DIM / 128, RS / 64), 256>>>(attn, Wo_s, nullptr, ys,
                                                ys2, RS, DIM, DIM, FLAG_RES);

    // 10) MLP up + bias + GELU
    gemm_f16<<<dim3(DFF / 128, RS / 64), 256>>>(ys2, W1, b1, nullptr,
                                                hbuf, RS, DFF, DIM, FLAG_BIAS | FLAG_GELU);

    // 11) MLP down + bias + residual
    gemm_f16<<<dim3(DIM / 128, RS / 64), 256>>>(hbuf, W2, b2, ys2,
                                                out, RS, DIM, DFF, FLAG_BIAS | FLAG_RES);
}

// round 12
// speedup vs baseline: 4.5396x; 1.4809x over previous
#include <cuda_runtime.h>
#include <cuda_bf16.h>
#include <cuda_fp16.h>
#include <math.h>
#include <stdint.h>

// Problem constants
#define FRAMES  256
#define PATCHES 64
#define DIM     512
#define HEADS   8
#define DH      64
#define DFF     1024
#define KL      128
#define TT      257
#define TS      65
#define RT      (PATCHES * TT)   // 16448
#define RS      (FRAMES * TS)    // 16640

#define FLAG_BIAS 1
#define FLAG_RES  2
#define FLAG_GELU 4

// -------------------- scratch --------------------------------------------
__device__ float g_xt   [RT * DIM];
__device__ float g_qkv  [RS * 3 * DIM];
__device__ float g_yt   [RT * DIM];
__device__ float g_ys   [RS * DIM];
__device__ float g_ys2  [RS * DIM];
__device__ float g_kproj[FRAMES * KL * DIM];
__device__ float g_vproj[FRAMES * KL * DIM];
// fp16 activations (GEMM A inputs)
__device__ __align__(16) __half g_xth  [RT * DIM];
__device__ __align__(16) __half g_ysh  [RS * DIM];
__device__ __align__(16) __half g_attnh[RS * DIM];
__device__ __align__(16) __half g_ys2h [RS * DIM];
__device__ __align__(16) __half g_hh   [RS * DFF];
// fp16 weights
__device__ __align__(16) __half g_hWqkv_t[DIM * 3 * DIM];
__device__ __align__(16) __half g_hWo_t  [DIM * DIM];
__device__ __align__(16) __half g_hWqkv_s[DIM * 3 * DIM];
__device__ __align__(16) __half g_hWo_s  [DIM * DIM];
__device__ __align__(16) __half g_hW1    [DIM * DFF];
__device__ __align__(16) __half g_hW2    [DFF * DIM];

// -------------------- helpers --------------------------------------------
__device__ __forceinline__ float f2tf32(float x) {
    uint32_t u;
    asm("cvt.rna.tf32.f32 %0, %1;" : "=r"(u) : "f"(x));
    return __uint_as_float(u);
}

__device__ __forceinline__ void mma_tf32(float (&c)[4], const uint32_t (&a)[4],
                                         const uint32_t (&b)[2]) {
    asm volatile(
        "mma.sync.aligned.m16n8k8.row.col.f32.tf32.tf32.f32 "
        "{%0,%1,%2,%3}, {%4,%5,%6,%7}, {%8,%9}, {%0,%1,%2,%3};"
        : "+f"(c[0]), "+f"(c[1]), "+f"(c[2]), "+f"(c[3])
        : "r"(a[0]), "r"(a[1]), "r"(a[2]), "r"(a[3]), "r"(b[0]), "r"(b[1]));
}

__device__ __forceinline__ void mma_f16(float (&c)[4], const uint32_t (&a)[4],
                                        uint32_t b0, uint32_t b1) {
    asm volatile(
        "mma.sync.aligned.m16n8k16.row.col.f32.f16.f16.f32 "
        "{%0,%1,%2,%3}, {%4,%5,%6,%7}, {%8,%9}, {%0,%1,%2,%3};"
        : "+f"(c[0]), "+f"(c[1]), "+f"(c[2]), "+f"(c[3])
        : "r"(a[0]), "r"(a[1]), "r"(a[2]), "r"(a[3]), "r"(b0), "r"(b1));
}

__device__ __forceinline__ void ldsm4(uint32_t (&r)[4], uint32_t addr) {
    asm volatile("ldmatrix.sync.aligned.m8n8.x4.shared.b16 {%0,%1,%2,%3}, [%4];"
        : "=r"(r[0]), "=r"(r[1]), "=r"(r[2]), "=r"(r[3]) : "r"(addr));
}
__device__ __forceinline__ void ldsm4t(uint32_t (&r)[4], uint32_t addr) {
    asm volatile("ldmatrix.sync.aligned.m8n8.x4.trans.shared.b16 {%0,%1,%2,%3}, [%4];"
        : "=r"(r[0]), "=r"(r[1]), "=r"(r[2]), "=r"(r[3]) : "r"(addr));
}

__device__ __forceinline__ uint32_t h2u(__half2 h) { return *(uint32_t*)&h; }

#define CPA16(dst, src) \
    asm volatile("cp.async.cg.shared.global [%0], [%1], 16;" :: "r"(dst), "l"(src))
#define CP_COMMIT() asm volatile("cp.async.commit_group;")
#define CP_WAIT(n)  asm volatile("cp.async.wait_group %0;" :: "n"(n))

// -------------------- fp32 -> fp16 convert --------------------------------
__global__ void cvt16(const float* __restrict__ s, __half* __restrict__ d, int n)
{
    int i = (blockIdx.x * 256 + threadIdx.x) * 8;
    if (i >= n) return;
    float4 a = *(const float4*)(s + i), b = *(const float4*)(s + i + 4);
    uint4 u = make_uint4(
        h2u(__floats2half2_rn(a.x, a.y)), h2u(__floats2half2_rn(a.z, a.w)),
        h2u(__floats2half2_rn(b.x, b.y)), h2u(__floats2half2_rn(b.z, b.w)));
    *(uint4*)(d + i) = u;
}

// -------------------- fp16 GEMM: cp.async pipeline + ldmatrix -------------
// C = A @ B (+bias)(+gelu)(+res). A,B fp16 (pre-converted); C fp32 and/or fp16.
// Block tile 64x128x32; STAGES-deep cp.async pipeline.
#define HAS 40
#define HBS 136
#define ASZ (64 * HAS)   // halves per A stage (5120 B)
#define BSZ (32 * HBS)   // halves per B stage (8704 B)
#define STAGES 3

__global__ __launch_bounds__(256) void gemm_h(
    const __half* __restrict__ A, const __half* __restrict__ B,
    const float* __restrict__ bias, const float* __restrict__ R,
    float* __restrict__ C, __half* __restrict__ Ch,
    int M, int N, int K, int flags)
{
    __shared__ __align__(16) __half As[STAGES * ASZ];
    __shared__ __align__(16) __half Bs[STAGES * BSZ];

    int tid = threadIdx.x;
    int warp = tid >> 5, lane = tid & 31;
    int wr = warp & 1;            // 2 warp-rows x 32
    int wc = warp >> 1;           // 4 warp-cols x 32
    int r0 = blockIdx.y * 64;
    int c0 = blockIdx.x * 128;
    int g = lane >> 2, tg = lane & 3;

    float acc[2][4][4];
    #pragma unroll
    for (int mt = 0; mt < 2; mt++)
        #pragma unroll
        for (int nt = 0; nt < 4; nt++)
            #pragma unroll
            for (int i = 0; i < 4; i++) acc[mt][nt][i] = 0.0f;

    // cp.async source/dest (per thread)
    int ar = tid >> 2, ac = (tid & 3) * 8;          // A: 64 rows x 4 chunks
    const __half* aSrc = A + (size_t)(r0 + ar) * K + ac;
    int br_ = tid >> 4, bc_ = (tid & 15) * 8;       // B: rows 0..15 (+16), 16 chunks
    const __half* bSrc0 = B + (size_t)br_ * N + c0 + bc_;
    const __half* bSrc1 = B + (size_t)(br_ + 16) * N + c0 + bc_;
    uint32_t aDst  = (uint32_t)__cvta_generic_to_shared(&As[ar * HAS + ac]);
    uint32_t bDst0 = (uint32_t)__cvta_generic_to_shared(&Bs[br_ * HBS + bc_]);
    uint32_t bDst1 = (uint32_t)__cvta_generic_to_shared(&Bs[(br_ + 16) * HBS + bc_]);

    // prologue: stages 0..STAGES-2
    #pragma unroll
    for (int s = 0; s < STAGES - 1; s++) {
        int k0 = s * 32;
        CPA16(aDst + s * (ASZ * 2), aSrc + k0);
        CPA16(bDst0 + s * (BSZ * 2), bSrc0 + (size_t)k0 * N);
        CPA16(bDst1 + s * (BSZ * 2), bSrc1 + (size_t)k0 * N);
        CP_COMMIT();
    }

    // ldmatrix per-lane base addresses
    int l15 = lane & 15, lhi = lane >> 4;
    uint32_t aAddr = (uint32_t)__cvta_generic_to_shared(As)
                   + (uint32_t)(((wr * 32 + l15) * HAS + lhi * 8) * 2);
    int bq = (lane & 7) + ((lane >> 3) & 1) * 8;
    uint32_t bAddr = (uint32_t)__cvta_generic_to_shared(Bs)
                   + (uint32_t)((bq * HBS + wc * 32 + lhi * 8) * 2);

    int buf = 0;
    for (int k0 = 0; k0 < K; k0 += 32) {
        CP_WAIT(STAGES - 2);
        __syncthreads();

        int kn = k0 + (STAGES - 1) * 32;
        if (kn < K) {
            int s = buf + (STAGES - 1); if (s >= STAGES) s -= STAGES;
            CPA16(aDst + s * (ASZ * 2), aSrc + kn);
            CPA16(bDst0 + s * (BSZ * 2), bSrc0 + (size_t)kn * N);
            CPA16(bDst1 + s * (BSZ * 2), bSrc1 + (size_t)kn * N);
        }
        CP_COMMIT();

        uint32_t aB = aAddr + buf * (ASZ * 2);
        uint32_t bB = bAddr + buf * (BSZ * 2);
        #pragma unroll
        for (int kk = 0; kk < 32; kk += 16) {
            uint32_t a[2][4], b[2][4];
            ldsm4 (a[0], aB + kk * 2);
            ldsm4 (a[1], aB + kk * 2 + 16 * HAS * 2);
            ldsm4t(b[0], bB + kk * HBS * 2);
            ldsm4t(b[1], bB + kk * HBS * 2 + 16 * 2);
            #pragma unroll
            for (int mt = 0; mt < 2; mt++)
                #pragma unroll
                for (int nt = 0; nt < 4; nt++)
                    mma_f16(acc[mt][nt], a[mt],
                            b[nt >> 1][(nt & 1) * 2], b[nt >> 1][(nt & 1) * 2 + 1]);
        }
        buf++; if (buf == STAGES) buf = 0;
    }

    // epilogue
    #pragma unroll
    for (int mt = 0; mt < 2; mt++) {
        #pragma unroll
        for (int nt = 0; nt < 4; nt++) {
            int col = c0 + wc * 32 + nt * 8 + 2 * tg;
            #pragma unroll
            for (int half = 0; half < 2; half++) {
                int row = r0 + wr * 32 + mt * 16 + g + half * 8;
                float v0 = acc[mt][nt][half * 2 + 0];
                float v1 = acc[mt][nt][half * 2 + 1];
                if (flags & FLAG_BIAS) { v0 += bias[col]; v1 += bias[col + 1]; }
                if (flags & FLAG_GELU) {
                    v0 = 0.5f * v0 * (1.0f + erff(v0 * 0.70710678118654752f));
                    v1 = 0.5f * v1 * (1.0f + erff(v1 * 0.70710678118654752f));
                }
                if (flags & FLAG_RES) {
                    float2 rr = *(const float2*)&R[(size_t)row * N + col];
                    v0 += rr.x; v1 += rr.y;
                }
                if (C)
                    *(float2*)&C[(size_t)row * N + col] = make_float2(v0, v1);
                if (Ch)
                    *(__half2*)&Ch[(size_t)row * N + col] = __floats2half2_rn(v0, v1);
            }
        }
    }
}

// -------------------- tensor-core attention (tf32) — fp16 output ----------
__global__ __launch_bounds__(256) void attn_mma(
    const float* __restrict__ Q, int qStride,
    const float* __restrict__ Kp, const float* __restrict__ Vp, int kvStride,
    __half* __restrict__ O, int Tq, int Tk, int ktiles, float scale)
{
    extern __shared__ float sm[];
    const int SST = ktiles * 64 + 4;
    float* Ssm  = sm;
    float* KVs  = sm + 64 * SST;
    float* srow = KVs + 64 * 68;

    int qt = blockIdx.x, b = blockIdx.y, h = blockIdx.z;
    int tid = threadIdx.x, warp = tid >> 5, lane = tid & 31;
    int g = lane >> 2, tg = lane & 3;
    int wm = warp >> 1, wn = warp & 1;
    int rb = wm * 16;
    int q0 = qt * 64;

    const float* Qb = Q  + (size_t)b * Tq * qStride  + h * DH;
    const float* Kb = Kp + (size_t)b * Tk * kvStride + h * DH;
    const float* Vb = Vp + (size_t)b * Tk * kvStride + h * DH;

    for (int i = tid; i < 64 * 16; i += 256) {
        int r = i >> 4, c4 = (i & 15) * 4;
        int rq = q0 + r; if (rq > Tq - 1) rq = Tq - 1;
        float4 v = *(const float4*)&Qb[(size_t)rq * qStride + c4];
        *(float4*)&KVs[r * 68 + c4] = make_float4(
            f2tf32(v.x * scale), f2tf32(v.y * scale),
            f2tf32(v.z * scale), f2tf32(v.w * scale));
    }
    __syncthreads();

    uint32_t aq[8][4];
    #pragma unroll
    for (int ks = 0; ks < 8; ks++) {
        aq[ks][0] = __float_as_uint(KVs[(rb + g)     * 68 + ks * 8 + tg]);
        aq[ks][1] = __float_as_uint(KVs[(rb + g + 8) * 68 + ks * 8 + tg]);
        aq[ks][2] = __float_as_uint(KVs[(rb + g)     * 68 + ks * 8 + tg + 4]);
        aq[ks][3] = __float_as_uint(KVs[(rb + g + 8) * 68 + ks * 8 + tg + 4]);
    }

    for (int kt = 0; kt < ktiles; kt++) {
        __syncthreads();
        for (int i = tid; i < 64 * 16; i += 256) {
            int r = i >> 4, c4 = (i & 15) * 4;
            int rk = kt * 64 + r; if (rk > Tk - 1) rk = Tk - 1;
            float4 v = *(const float4*)&Kb[(size_t)rk * kvStride + c4];
            *(float4*)&KVs[r * 68 + c4] = make_float4(
                f2tf32(v.x), f2tf32(v.y), f2tf32(v.z), f2tf32(v.w));
        }
        __syncthreads();

        float cS[4][4];
        #pragma unroll
        for (int nt = 0; nt < 4; nt++)
            #pragma unroll
            for (int i = 0; i < 4; i++) cS[nt][i] = 0.0f;

        #pragma unroll
        for (int ks = 0; ks < 8; ks++) {
            uint32_t bf[4][2];
            #pragma unroll
            for (int nt = 0; nt < 4; nt++) {
                int n0 = wn * 32 + nt * 8;
                bf[nt][0] = __float_as_uint(KVs[(n0 + g) * 68 + ks * 8 + tg]);
                bf[nt][1] = __float_as_uint(KVs[(n0 + g) * 68 + ks * 8 + tg + 4]);
            }
            #pragma unroll
            for (int nt = 0; nt < 4; nt++)
                mma_tf32(cS[nt], aq[ks], bf[nt]);
        }

        #pragma unroll
        for (int nt = 0; nt < 4; nt++) {
            int cl = wn * 32 + nt * 8 + 2 * tg;
            int cg = kt * 64 + cl;
            bool ok0 = cg < Tk, ok1 = cg + 1 < Tk;
            *(float2*)&Ssm[(rb + g) * SST + kt * 64 + cl] =
                make_float2(ok0 ? cS[nt][0] : -1e30f, ok1 ? cS[nt][1] : -1e30f);
            *(float2*)&Ssm[(rb + g + 8) * SST + kt * 64 + cl] =
                make_float2(ok0 ? cS[nt][2] : -1e30f, ok1 ? cS[nt][3] : -1e30f);
        }
    }
    __syncthreads();

    {
        int row = tid >> 2, sub = tid & 3;
        float* Sr = &Ssm[row * SST];
        int nc = ktiles * 64;
        float m = -1e30f;
        for (int c = sub; c < nc; c += 4) m = fmaxf(m, Sr[c]);
        m = fmaxf(m, __shfl_xor_sync(0xffffffffu, m, 1));
        m = fmaxf(m, __shfl_xor_sync(0xffffffffu, m, 2));
        float s = 0.0f;
        for (int c = sub; c < nc; c += 4) {
            float e = __expf(Sr[c] - m);
            s += e;
            Sr[c] = f2tf32(e);
        }
        s += __shfl_xor_sync(0xffffffffu, s, 1);
        s += __shfl_xor_sync(0xffffffffu, s, 2);
        if (sub == 0) srow[row] = 1.0f / s;
    }
    __syncthreads();

    float inv0 = srow[rb + g], inv1 = srow[rb + g + 8];

    float cO[4][4];
    #pragma unroll
    for (int nt = 0; nt < 4; nt++)
        #pragma unroll
        for (int i = 0; i < 4; i++) cO[nt][i] = 0.0f;

    for (int kt = 0; kt < ktiles; kt++) {
        __syncthreads();
        for (int i = tid; i < 64 * 16; i += 256) {
            int r = i >> 4, c4 = (i & 15) * 4;
            int rk = kt * 64 + r; if (rk > Tk - 1) rk = Tk - 1;
            float4 v = *(const float4*)&Vb[(size_t)rk * kvStride + c4];
            *(float4*)&KVs[r * 68 + c4] = make_float4(
                f2tf32(v.x), f2tf32(v.y), f2tf32(v.z), f2tf32(v.w));
        }
        __syncthreads();

        #pragma unroll
        for (int ks = 0; ks < 8; ks++) {
            uint32_t ap[4];
            int kb = kt * 64 + ks * 8;
            ap[0] = __float_as_uint(Ssm[(rb + g)     * SST + kb + tg]);
            ap[1] = __float_as_uint(Ssm[(rb + g + 8) * SST + kb + tg]);
            ap[2] = __float_as_uint(Ssm[(rb + g)     * SST + kb + tg + 4]);
            ap[3] = __float_as_uint(Ssm[(rb + g + 8) * SST + kb + tg + 4]);
            #pragma unroll
            for (int nt = 0; nt < 4; nt++) {
                int n0 = wn * 32 + nt * 8;
                uint32_t bv[2];
                bv[0] = __float_as_uint(KVs[(ks * 8 + tg)     * 68 + n0 + g]);
                bv[1] = __float_as_uint(KVs[(ks * 8 + tg + 4) * 68 + n0 + g]);
                mma_tf32(cO[nt], ap, bv);
            }
        }
    }

    #pragma unroll
    for (int nt = 0; nt < 4; nt++) {
        int dl = wn * 32 + nt * 8 + 2 * tg;
        int r0g = q0 + rb + g;
        if (r0g < Tq)
            *(__half2*)&O[((size_t)b * Tq + r0g) * DIM + h * DH + dl] =
                __floats2half2_rn(cO[nt][0] * inv0, cO[nt][1] * inv0);
        int r1g = q0 + rb + g + 8;
        if (r1g < Tq)
            *(__half2*)&O[((size_t)b * Tq + r1g) * DIM + h * DH + dl] =
                __floats2half2_rn(cO[nt][2] * inv1, cO[nt][3] * inv1);
    }
}

// -------------------- Linformer K/V projection ----------------------------
__global__ __launch_bounds__(256) void linproj_kernel(
    const float* __restrict__ qkv, const float* __restrict__ E,
    float* __restrict__ kproj, float* __restrict__ vproj)
{
    __shared__ float Es[TS * 32];
    __shared__ float Ksm[TS * 64];

    int b = blockIdx.x;
    int c0 = blockIdx.y * 64;
    int zz = blockIdx.z;
    int kvsel = zz & 1;
    int kkt = zz >> 1;
    int tid = threadIdx.x;

    int colbase = DIM + kvsel * DIM + c0;
    for (int i = tid; i < TS * 64; i += 256) {
        int j = i >> 6, c = i & 63;
        Ksm[i] = qkv[((size_t)b * TS + j) * (3 * DIM) + colbase + c];
    }
    for (int i = tid; i < TS * 32; i += 256) {
        int j = i >> 5, q = i & 31;
        Es[i] = E[j * KL + kkt * 32 + q];
    }
    __syncthreads();

    int c = tid & 63, kg = tid >> 6;
    float acc[8];
    #pragma unroll
    for (int i = 0; i < 8; i++) acc[i] = 0.0f;

    for (int j = 0; j < TS; j++) {
        float kv = Ksm[j * 64 + c];
        #pragma unroll
        for (int i = 0; i < 8; i++)
            acc[i] += kv * Es[j * 32 + kg * 8 + i];
    }

    float* dst = kvsel ? vproj : kproj;
    #pragma unroll
    for (int i = 0; i < 8; i++) {
        int kk = kkt * 32 + kg * 8 + i;
        dst[((size_t)b * KL + kk) * DIM + c0 + c] = acc[i];
    }
}

// -------------------- token rearrangement (fp32 + fp16 outputs) -----------
__global__ void gather_t_kernel(const float* __restrict__ x,
                                float* __restrict__ xt, __half* __restrict__ xth)
{
    int row = blockIdx.x;
    int p = row / TT, t = row % TT;
    const float4* s = (const float4*)(t == 0 ? x
                        : x + (size_t)(1 + (t - 1) * PATCHES + p) * DIM);
    float4 v = s[threadIdx.x];
    ((float4*)(xt + (size_t)row * DIM))[threadIdx.x] = v;
    uint2 h = make_uint2(h2u(__floats2half2_rn(v.x, v.y)),
                         h2u(__floats2half2_rn(v.z, v.w)));
    *(uint2*)(xth + (size_t)row * DIM + threadIdx.x * 4) = h;
}

__global__ void gather_s_kernel(const float* __restrict__ yt,
                                float* __restrict__ ys, __half* __restrict__ ysh)
{
    int row = blockIdx.x;
    int f = row / TS, t = row % TS;
    const float* src = (t == 0)
        ? yt + (size_t)((f & 63) * TT) * DIM
        : yt + (size_t)((t - 1) * TT + 1 + f) * DIM;
    float4 v = ((const float4*)src)[threadIdx.x];
    ((float4*)(ys + (size_t)row * DIM))[threadIdx.x] = v;
    uint2 h = make_uint2(h2u(__floats2half2_rn(v.x, v.y)),
                         h2u(__floats2half2_rn(v.z, v.w)));
    *(uint2*)(ysh + (size_t)row * DIM + threadIdx.x * 4) = h;
}

// -------------------- launch ----------------------------------------------
extern "C" void kernel_launch(void* const* d_in, const int* in_sizes, int n_in,
                              void* d_out, int out_size)
{
    const float* x      = (const float*)d_in[0];
    const float* Wqkv_t = (const float*)d_in[1];
    const float* Wo_t   = (const float*)d_in[2];
    const float* Wqkv_s = (const float*)d_in[3];
    const float* Wo_s   = (const float*)d_in[4];
    const float* E      = (const float*)d_in[5];
    const float* W1     = (const float*)d_in[6];
    const float* b1     = (const float*)d_in[7];
    const float* W2     = (const float*)d_in[8];
    const float* b2     = (const float*)d_in[9];
    float* out = (float*)d_out;

    float *xt, *qkv, *yt, *ys, *ys2, *kproj, *vproj;
    __half *xth, *ysh, *attnh, *ys2h, *hh;
    __half *hQt, *hOt, *hQs, *hOs, *hW1, *hW2;
    cudaGetSymbolAddress((void**)&xt,    g_xt);
    cudaGetSymbolAddress((void**)&qkv,   g_qkv);
    cudaGetSymbolAddress((void**)&yt,    g_yt);
    cudaGetSymbolAddress((void**)&ys,    g_ys);
    cudaGetSymbolAddress((void**)&ys2,   g_ys2);
    cudaGetSymbolAddress((void**)&kproj, g_kproj);
    cudaGetSymbolAddress((void**)&vproj, g_vproj);
    cudaGetSymbolAddress((void**)&xth,   g_xth);
    cudaGetSymbolAddress((void**)&ysh,   g_ysh);
    cudaGetSymbolAddress((void**)&attnh, g_attnh);
    cudaGetSymbolAddress((void**)&ys2h,  g_ys2h);
    cudaGetSymbolAddress((void**)&hh,    g_hh);
    cudaGetSymbolAddress((void**)&hQt,   g_hWqkv_t);
    cudaGetSymbolAddress((void**)&hOt,   g_hWo_t);
    cudaGetSymbolAddress((void**)&hQs,   g_hWqkv_s);
    cudaGetSymbolAddress((void**)&hOs,   g_hWo_s);
    cudaGetSymbolAddress((void**)&hW1,   g_hW1);
    cudaGetSymbolAddress((void**)&hW2,   g_hW2);

    const int ktT = (TT + 63) / 64;          // 5
    const int ktS = (KL + 63) / 64;          // 2
    const int qtT = (TT + 63) / 64;          // 5
    const int qtS = (TS + 63) / 64;          // 2
    const int smemT = (64 * (ktT * 64 + 4) + 64 * 68 + 64) * (int)sizeof(float);
    const int smemS = (64 * (ktS * 64 + 4) + 64 * 68 + 64) * (int)sizeof(float);
    cudaFuncSetAttribute(attn_mma, cudaFuncAttributeMaxDynamicSharedMemorySize, smemT);

    // 0) convert weights to fp16
    auto cgrid = [](int n) { return (n / 8 + 255) / 256; };
    cvt16<<<cgrid(DIM * 3 * DIM), 256>>>(Wqkv_t, hQt, DIM * 3 * DIM);
    cvt16<<<cgrid(DIM * DIM), 256>>>(Wo_t, hOt, DIM * DIM);
    cvt16<<<cgrid(DIM * 3 * DIM), 256>>>(Wqkv_s, hQs, DIM * 3 * DIM);
    cvt16<<<cgrid(DIM * DIM), 256>>>(Wo_s, hOs, DIM * DIM);
    cvt16<<<cgrid(DIM * DFF), 256>>>(W1, hW1, DIM * DFF);
    cvt16<<<cgrid(DFF * DIM), 256>>>(W2, hW2, DFF * DIM);

    // 1) temporal token gather (fp32 + fp16)
    gather_t_kernel<<<RT, 128>>>(x, xt, xth);

    // 2) temporal QKV
    gemm_h<<<dim3(3 * DIM / 128, RT / 64), 256>>>(
        xth, hQt, nullptr, nullptr, qkv, nullptr, RT, 3 * DIM, DIM, 0);

    // 3) temporal attention -> fp16 output
    attn_mma<<<dim3(qtT, PATCHES, HEADS), 256, smemT>>>(
        qkv, 3 * DIM, qkv + DIM, qkv + 2 * DIM, 3 * DIM, attnh, TT, TT, ktT, 0.125f);

    // 4) Wo_t + residual
    gemm_h<<<dim3(DIM / 128, RT / 64), 256>>>(
        attnh, hOt, nullptr, xt, yt, nullptr, RT, DIM, DIM, FLAG_RES);

    // 5) spatial gather (fp32 + fp16)
    gather_s_kernel<<<RS, 128>>>(yt, ys, ysh);

    // 6) spatial QKV
    gemm_h<<<dim3(3 * DIM / 128, RS / 64), 256>>>(
        ysh, hQs, nullptr, nullptr, qkv, nullptr, RS, 3 * DIM, DIM, 0);

    // 7) Linformer K/V projection
    linproj_kernel<<<dim3(FRAMES, DIM / 64, 8), 256>>>(qkv, E, kproj, vproj);

    // 8) spatial attention (2 query tiles) -> fp16 output
    attn_mma<<<dim3(qtS, FRAMES, HEADS), 256, smemS>>>(
        qkv, 3 * DIM, kproj, vproj, DIM, attnh, TS, KL, ktS, 0.125f);

    // 9) Wo_s + residual (fp32 for residual chain, fp16 for MLP A)
    gemm_h<<<dim3(DIM / 128, RS / 64), 256>>>(
        attnh, hOs, nullptr, ys, ys2, ys2h, RS, DIM, DIM, FLAG_RES);

    // 10) MLP up + bias + GELU (fp16-only output)
    gemm_h<<<dim3(DFF / 128, RS / 64), 256>>>(
        ys2h, hW1, b1, nullptr, nullptr, hh, RS, DFF, DIM, FLAG_BIAS | FLAG_GELU);

    // 11) MLP down + bias + residual -> final fp32 output
    gemm_h<<<dim3(DIM / 128, RS / 64), 256>>>(
        hh, hW2, b2, ys2, out, nullptr, RS, DIM, DFF, FLAG_BIAS | FLAG_RES);
}

// round 13
// speedup vs baseline: 6.4065x; 1.4113x over previous
#include <cuda_runtime.h>
#include <cuda_bf16.h>
#include <cuda_fp16.h>
#include <math.h>
#include <stdint.h>

// Problem constants
#define FRAMES  256
#define PATCHES 64
#define DIM     512
#define HEADS   8
#define DH      64
#define DFF     1024
#define KL      128
#define TT      257
#define TS      65
#define RT      (PATCHES * TT)   // 16448
#define RS      (FRAMES * TS)    // 16640

#define FLAG_BIAS 1
#define FLAG_RES  2
#define FLAG_GELU 4

// -------------------- scratch --------------------------------------------
__device__ float g_xt   [RT * DIM];
__device__ float g_yt   [RT * DIM];
__device__ float g_ys   [RS * DIM];
__device__ float g_ys2  [RS * DIM];
// fp16 activations
__device__ __align__(16) __half g_xth  [RT * DIM];
__device__ __align__(16) __half g_ysh  [RS * DIM];
__device__ __align__(16) __half g_qkvh [RS * 3 * DIM];
__device__ __align__(16) __half g_attnh[RS * DIM];
__device__ __align__(16) __half g_ys2h [RS * DIM];
__device__ __align__(16) __half g_hh   [RS * DFF];
__device__ __align__(16) __half g_kprojh[FRAMES * KL * DIM];
__device__ __align__(16) __half g_vprojh[FRAMES * KL * DIM];
// fp16 weights
__device__ __align__(16) __half g_hWqkv_t[DIM * 3 * DIM];
__device__ __align__(16) __half g_hWo_t  [DIM * DIM];
__device__ __align__(16) __half g_hWqkv_s[DIM * 3 * DIM];
__device__ __align__(16) __half g_hWo_s  [DIM * DIM];
__device__ __align__(16) __half g_hW1    [DIM * DFF];
__device__ __align__(16) __half g_hW2    [DFF * DIM];

// -------------------- helpers --------------------------------------------
__device__ __forceinline__ void mma_f16(float (&c)[4], const uint32_t (&a)[4],
                                        uint32_t b0, uint32_t b1) {
    asm volatile(
        "mma.sync.aligned.m16n8k16.row.col.f32.f16.f16.f32 "
        "{%0,%1,%2,%3}, {%4,%5,%6,%7}, {%8,%9}, {%0,%1,%2,%3};"
        : "+f"(c[0]), "+f"(c[1]), "+f"(c[2]), "+f"(c[3])
        : "r"(a[0]), "r"(a[1]), "r"(a[2]), "r"(a[3]), "r"(b0), "r"(b1));
}

__device__ __forceinline__ void ldsm4(uint32_t (&r)[4], uint32_t addr) {
    asm volatile("ldmatrix.sync.aligned.m8n8.x4.shared.b16 {%0,%1,%2,%3}, [%4];"
        : "=r"(r[0]), "=r"(r[1]), "=r"(r[2]), "=r"(r[3]) : "r"(addr));
}
__device__ __forceinline__ void ldsm4t(uint32_t (&r)[4], uint32_t addr) {
    asm volatile("ldmatrix.sync.aligned.m8n8.x4.trans.shared.b16 {%0,%1,%2,%3}, [%4];"
        : "=r"(r[0]), "=r"(r[1]), "=r"(r[2]), "=r"(r[3]) : "r"(addr));
}

__device__ __forceinline__ uint32_t h2u(__half2 h) { return *(uint32_t*)&h; }

#define CPA16(dst, src) \
    asm volatile("cp.async.cg.shared.global [%0], [%1], 16;" :: "r"(dst), "l"(src))
#define CP_COMMIT() asm volatile("cp.async.commit_group;")
#define CP_WAIT(n)  asm volatile("cp.async.wait_group %0;" :: "n"(n))

// -------------------- fp32 -> fp16 convert --------------------------------
__global__ void cvt16(const float* __restrict__ s, __half* __restrict__ d, int n)
{
    int i = (blockIdx.x * 256 + threadIdx.x) * 8;
    if (i >= n) return;
    float4 a = *(const float4*)(s + i), b = *(const float4*)(s + i + 4);
    uint4 u = make_uint4(
        h2u(__floats2half2_rn(a.x, a.y)), h2u(__floats2half2_rn(a.z, a.w)),
        h2u(__floats2half2_rn(b.x, b.y)), h2u(__floats2half2_rn(b.z, b.w)));
    *(uint4*)(d + i) = u;
}

// -------------------- fp16 GEMM (verified) --------------------------------
#define HAS 40
#define HBS 136
#define ASZ (64 * HAS)
#define BSZ (32 * HBS)
#define STAGES 3

__global__ __launch_bounds__(256) void gemm_h(
    const __half* __restrict__ A, const __half* __restrict__ B,
    const float* __restrict__ bias, const float* __restrict__ R,
    float* __restrict__ C, __half* __restrict__ Ch,
    int M, int N, int K, int flags)
{
    __shared__ __align__(16) __half As[STAGES * ASZ];
    __shared__ __align__(16) __half Bs[STAGES * BSZ];

    int tid = threadIdx.x;
    int warp = tid >> 5, lane = tid & 31;
    int wr = warp & 1;
    int wc = warp >> 1;
    int r0 = blockIdx.y * 64;
    int c0 = blockIdx.x * 128;
    int g = lane >> 2, tg = lane & 3;

    float acc[2][4][4];
    #pragma unroll
    for (int mt = 0; mt < 2; mt++)
        #pragma unroll
        for (int nt = 0; nt < 4; nt++)
            #pragma unroll
            for (int i = 0; i < 4; i++) acc[mt][nt][i] = 0.0f;

    int ar = tid >> 2, ac = (tid & 3) * 8;
    const __half* aSrc = A + (size_t)(r0 + ar) * K + ac;
    int br_ = tid >> 4, bc_ = (tid & 15) * 8;
    const __half* bSrc0 = B + (size_t)br_ * N + c0 + bc_;
    const __half* bSrc1 = B + (size_t)(br_ + 16) * N + c0 + bc_;
    uint32_t aDst  = (uint32_t)__cvta_generic_to_shared(&As[ar * HAS + ac]);
    uint32_t bDst0 = (uint32_t)__cvta_generic_to_shared(&Bs[br_ * HBS + bc_]);
    uint32_t bDst1 = (uint32_t)__cvta_generic_to_shared(&Bs[(br_ + 16) * HBS + bc_]);

    #pragma unroll
    for (int s = 0; s < STAGES - 1; s++) {
        int k0 = s * 32;
        CPA16(aDst + s * (ASZ * 2), aSrc + k0);
        CPA16(bDst0 + s * (BSZ * 2), bSrc0 + (size_t)k0 * N);
        CPA16(bDst1 + s * (BSZ * 2), bSrc1 + (size_t)k0 * N);
        CP_COMMIT();
    }

    int l15 = lane & 15, lhi = lane >> 4;
    uint32_t aAddr = (uint32_t)__cvta_generic_to_shared(As)
                   + (uint32_t)(((wr * 32 + l15) * HAS + lhi * 8) * 2);
    int bq = (lane & 7) + ((lane >> 3) & 1) * 8;
    uint32_t bAddr = (uint32_t)__cvta_generic_to_shared(Bs)
                   + (uint32_t)((bq * HBS + wc * 32 + lhi * 8) * 2);

    int buf = 0;
    for (int k0 = 0; k0 < K; k0 += 32) {
        CP_WAIT(STAGES - 2);
        __syncthreads();

        int kn = k0 + (STAGES - 1) * 32;
        if (kn < K) {
            int s = buf + (STAGES - 1); if (s >= STAGES) s -= STAGES;
            CPA16(aDst + s * (ASZ * 2), aSrc + kn);
            CPA16(bDst0 + s * (BSZ * 2), bSrc0 + (size_t)kn * N);
            CPA16(bDst1 + s * (BSZ * 2), bSrc1 + (size_t)kn * N);
        }
        CP_COMMIT();

        uint32_t aB = aAddr + buf * (ASZ * 2);
        uint32_t bB = bAddr + buf * (BSZ * 2);
        #pragma unroll
        for (int kk = 0; kk < 32; kk += 16) {
            uint32_t a[2][4], b[2][4];
            ldsm4 (a[0], aB + kk * 2);
            ldsm4 (a[1], aB + kk * 2 + 16 * HAS * 2);
            ldsm4t(b[0], bB + kk * HBS * 2);
            ldsm4t(b[1], bB + kk * HBS * 2 + 16 * 2);
            #pragma unroll
            for (int mt = 0; mt < 2; mt++)
                #pragma unroll
                for (int nt = 0; nt < 4; nt++)
                    mma_f16(acc[mt][nt], a[mt],
                            b[nt >> 1][(nt & 1) * 2], b[nt >> 1][(nt & 1) * 2 + 1]);
        }
        buf++; if (buf == STAGES) buf = 0;
    }

    #pragma unroll
    for (int mt = 0; mt < 2; mt++) {
        #pragma unroll
        for (int nt = 0; nt < 4; nt++) {
            int col = c0 + wc * 32 + nt * 8 + 2 * tg;
            #pragma unroll
            for (int half = 0; half < 2; half++) {
                int row = r0 + wr * 32 + mt * 16 + g + half * 8;
                float v0 = acc[mt][nt][half * 2 + 0];
                float v1 = acc[mt][nt][half * 2 + 1];
                if (flags & FLAG_BIAS) { v0 += bias[col]; v1 += bias[col + 1]; }
                if (flags & FLAG_GELU) {
                    v0 = 0.5f * v0 * (1.0f + erff(v0 * 0.70710678118654752f));
                    v1 = 0.5f * v1 * (1.0f + erff(v1 * 0.70710678118654752f));
                }
                if (flags & FLAG_RES) {
                    float2 rr = *(const float2*)&R[(size_t)row * N + col];
                    v0 += rr.x; v1 += rr.y;
                }
                if (C)
                    *(float2*)&C[(size_t)row * N + col] = make_float2(v0, v1);
                if (Ch)
                    *(__half2*)&Ch[(size_t)row * N + col] = __floats2half2_rn(v0, v1);
            }
        }
    }
}

// -------------------- fp16 tensor-core attention ---------------------------
// One block = (64-q tile, batch, head). fp16 Q/K/V, fp16 S/P panel, fp32 softmax.
#define KVSTR 72                  // tile stride in halves (144B = 9x16B, odd)
#define KVSZ  (64 * KVSTR)

__global__ __launch_bounds__(256) void attn_h(
    const __half* __restrict__ Q, int qStride,
    const __half* __restrict__ Kp, const __half* __restrict__ Vp, int kvStride,
    __half* __restrict__ O, int Tq, int Tk, int ktiles, float scale)
{
    extern __shared__ __align__(16) char smh[];
    const int SSTh = ktiles * 64 + 8;            // odd multiple of 8 halves
    __half* Ssm = (__half*)smh;                              // 64 * SSTh halves
    __half* KV  = (__half*)(smh + (size_t)64 * SSTh * 2);    // 2 x KVSZ halves
    float*  srow = (float*)(smh + (size_t)64 * SSTh * 2 + 2 * KVSZ * 2);

    int qt = blockIdx.x, b = blockIdx.y, h = blockIdx.z;
    int tid = threadIdx.x, warp = tid >> 5, lane = tid & 31;
    int g = lane >> 2, tg = lane & 3;
    int wm = warp >> 1, wn = warp & 1;           // 4x2 warp grid
    int rb = wm * 16;
    int q0 = qt * 64;
    int l15 = lane & 15, lhi = lane >> 4;
    int bq = (lane & 7) + ((lane >> 3) & 1) * 8;

    const __half* Qb = Q  + (size_t)b * Tq * qStride  + h * DH;
    const __half* Kb = Kp + (size_t)b * Tk * kvStride + h * DH;
    const __half* Vb = Vp + (size_t)b * Tk * kvStride + h * DH;

    uint32_t kvBase = (uint32_t)__cvta_generic_to_shared(KV);
    uint32_t sBase  = (uint32_t)__cvta_generic_to_shared(Ssm);

    // per-thread tile-load geometry: row = tid>>2, 2x16B at col (tid&3)*16, +8
    int lr = tid >> 2, lc = (tid & 3) * 16;

    // ---- load Q tile (synchronous) ----
    {
        int rq = q0 + lr; if (rq > Tq - 1) rq = Tq - 1;
        const __half* src = Qb + (size_t)rq * qStride + lc;
        *(uint4*)&KV[lr * KVSTR + lc]     = *(const uint4*)src;
        *(uint4*)&KV[lr * KVSTR + lc + 8] = *(const uint4*)(src + 8);
    }
    __syncthreads();

    // Q fragments (A operand), all 4 k16-steps
    uint32_t aq[4][4];
    {
        uint32_t qA = kvBase + (uint32_t)(((rb + l15) * KVSTR + lhi * 8) * 2);
        #pragma unroll
        for (int kk = 0; kk < 4; kk++) ldsm4(aq[kk], qA + kk * 32);
    }
    __syncthreads();

    // cp.async prefetch helpers
    auto prefK = [&](int bf, int kt) {
        int rk = kt * 64 + lr; if (rk > Tk - 1) rk = Tk - 1;
        const __half* src = Kb + (size_t)rk * kvStride + lc;
        uint32_t dst = kvBase + (uint32_t)((bf * KVSZ + lr * KVSTR + lc) * 2);
        CPA16(dst, src);
        CPA16(dst + 16, src + 8);
        CP_COMMIT();
    };
    auto prefV = [&](int bf, int kt) {
        int rk = kt * 64 + lr; if (rk > Tk - 1) rk = Tk - 1;
        const __half* src = Vb + (size_t)rk * kvStride + lc;
        uint32_t dst = kvBase + (uint32_t)((bf * KVSZ + lr * KVSTR + lc) * 2);
        CPA16(dst, src);
        CPA16(dst + 16, src + 8);
        CP_COMMIT();
    };

    // ---- phase 1: S = Q K^T ----
    prefK(0, 0);
    for (int kt = 0; kt < ktiles; kt++) {
        if (kt + 1 < ktiles) { prefK((kt + 1) & 1, kt + 1); CP_WAIT(1); }
        else                 { CP_WAIT(0); }
        __syncthreads();

        float cS[4][4];
        #pragma unroll
        for (int nt = 0; nt < 4; nt++)
            #pragma unroll
            for (int i = 0; i < 4; i++) cS[nt][i] = 0.0f;

        uint32_t kB = kvBase + (uint32_t)(((kt & 1) * KVSZ
                     + (wn * 32 + l15) * KVSTR + lhi * 8) * 2);
        #pragma unroll
        for (int kk = 0; kk < 4; kk++) {
            uint32_t kb0[4], kb1[4];
            ldsm4(kb0, kB + kk * 32);
            ldsm4(kb1, kB + 16 * KVSTR * 2 + kk * 32);
            mma_f16(cS[0], aq[kk], kb0[0], kb0[2]);
            mma_f16(cS[1], aq[kk], kb0[1], kb0[3]);
            mma_f16(cS[2], aq[kk], kb1[0], kb1[2]);
            mma_f16(cS[3], aq[kk], kb1[1], kb1[3]);
        }

        // store scaled + masked scores (fp16)
        #pragma unroll
        for (int nt = 0; nt < 4; nt++) {
            int cl = wn * 32 + nt * 8 + 2 * tg;
            int cg = kt * 64 + cl;
            float s0 = (cg     < Tk) ? cS[nt][0] * scale : -60000.0f;
            float s1 = (cg + 1 < Tk) ? cS[nt][1] * scale : -60000.0f;
            float s2 = (cg     < Tk) ? cS[nt][2] * scale : -60000.0f;
            float s3 = (cg + 1 < Tk) ? cS[nt][3] * scale : -60000.0f;
            *(__half2*)&Ssm[(rb + g) * SSTh + kt * 64 + cl]     = __floats2half2_rn(s0, s1);
            *(__half2*)&Ssm[(rb + g + 8) * SSTh + kt * 64 + cl] = __floats2half2_rn(s2, s3);
        }
        __syncthreads();
    }

    // overlap V tile-0 load with softmax
    prefV(0, 0);

    // ---- phase 2: softmax (fp32 math over fp16 panel) ----
    {
        int row = tid >> 2, sub = tid & 3;
        __half2* Sr = (__half2*)&Ssm[row * SSTh];
        int nc2 = ktiles * 32;
        float m = -1e30f;
        for (int c = sub; c < nc2; c += 4) {
            float2 v = __half22float2(Sr[c]);
            m = fmaxf(m, fmaxf(v.x, v.y));
        }
        m = fmaxf(m, __shfl_xor_sync(0xffffffffu, m, 1));
        m = fmaxf(m, __shfl_xor_sync(0xffffffffu, m, 2));
        float s = 0.0f;
        for (int c = sub; c < nc2; c += 4) {
            float2 v = __half22float2(Sr[c]);
            float e0 = __expf(v.x - m), e1 = __expf(v.y - m);
            s += e0 + e1;
            Sr[c] = __floats2half2_rn(e0, e1);
        }
        s += __shfl_xor_sync(0xffffffffu, s, 1);
        s += __shfl_xor_sync(0xffffffffu, s, 2);
        if (sub == 0) srow[row] = 1.0f / s;
    }
    __syncthreads();

    // ---- phase 3: O = P V ----
    float cO[4][4];
    #pragma unroll
    for (int nt = 0; nt < 4; nt++)
        #pragma unroll
        for (int i = 0; i < 4; i++) cO[nt][i] = 0.0f;

    uint32_t pA = sBase + (uint32_t)(((rb + l15) * SSTh + lhi * 8) * 2);
    for (int kt = 0; kt < ktiles; kt++) {
        if (kt + 1 < ktiles) { prefV((kt + 1) & 1, kt + 1); CP_WAIT(1); }
        else                 { CP_WAIT(0); }
        __syncthreads();

        uint32_t vB = kvBase + (uint32_t)(((kt & 1) * KVSZ
                     + bq * KVSTR + wn * 32 + lhi * 8) * 2);
        #pragma unroll
        for (int kk = 0; kk < 4; kk++) {
            uint32_t ap[4];
            ldsm4(ap, pA + (kt * 64 + kk * 16) * 2);
            uint32_t vb0[4], vb1[4];
            ldsm4t(vb0, vB + kk * 16 * KVSTR * 2);
            ldsm4t(vb1, vB + kk * 16 * KVSTR * 2 + 32);
            mma_f16(cO[0], ap, vb0[0], vb0[1]);
            mma_f16(cO[1], ap, vb0[2], vb0[3]);
            mma_f16(cO[2], ap, vb1[0], vb1[1]);
            mma_f16(cO[3], ap, vb1[2], vb1[3]);
        }
        __syncthreads();
    }

    // ---- epilogue ----
    float inv0 = srow[rb + g], inv1 = srow[rb + g + 8];
    #pragma unroll
    for (int nt = 0; nt < 4; nt++) {
        int dl = wn * 32 + nt * 8 + 2 * tg;
        int r0g = q0 + rb + g;
        if (r0g < Tq)
            *(__half2*)&O[((size_t)b * Tq + r0g) * DIM + h * DH + dl] =
                __floats2half2_rn(cO[nt][0] * inv0, cO[nt][1] * inv0);
        int r1g = q0 + rb + g + 8;
        if (r1g < Tq)
            *(__half2*)&O[((size_t)b * Tq + r1g) * DIM + h * DH + dl] =
                __floats2half2_rn(cO[nt][2] * inv1, cO[nt][3] * inv1);
    }
}

// -------------------- Linformer K/V projection (fp16 I/O) ------------------
__global__ __launch_bounds__(256) void linproj_h(
    const __half* __restrict__ qkv, const float* __restrict__ E,
    __half* __restrict__ kproj, __half* __restrict__ vproj)
{
    __shared__ float Es[TS * 32];
    __shared__ float Ksm[TS * 64];

    int b = blockIdx.x;
    int c0 = blockIdx.y * 64;
    int zz = blockIdx.z;
    int kvsel = zz & 1;
    int kkt = zz >> 1;
    int tid = threadIdx.x;

    int colbase = DIM + kvsel * DIM + c0;
    for (int i = tid; i < TS * 64; i += 256) {
        int j = i >> 6, c = i & 63;
        Ksm[i] = __half2float(qkv[((size_t)b * TS + j) * (3 * DIM) + colbase + c]);
    }
    for (int i = tid; i < TS * 32; i += 256) {
        int j = i >> 5, q = i & 31;
        Es[i] = E[j * KL + kkt * 32 + q];
    }
    __syncthreads();

    int c = tid & 63, kg = tid >> 6;
    float acc[8];
    #pragma unroll
    for (int i = 0; i < 8; i++) acc[i] = 0.0f;

    for (int j = 0; j < TS; j++) {
        float kv = Ksm[j * 64 + c];
        #pragma unroll
        for (int i = 0; i < 8; i++)
            acc[i] += kv * Es[j * 32 + kg * 8 + i];
    }

    __half* dst = kvsel ? vproj : kproj;
    #pragma unroll
    for (int i = 0; i < 8; i++) {
        int kk = kkt * 32 + kg * 8 + i;
        dst[((size_t)b * KL + kk) * DIM + c0 + c] = __float2half_rn(acc[i]);
    }
}

// -------------------- token rearrangement ---------------------------------
__global__ void gather_t_kernel(const float* __restrict__ x,
                                float* __restrict__ xt, __half* __restrict__ xth)
{
    int row = blockIdx.x;
    int p = row / TT, t = row % TT;
    const float4* s = (const float4*)(t == 0 ? x
                        : x + (size_t)(1 + (t - 1) * PATCHES + p) * DIM);
    float4 v = s[threadIdx.x];
    ((float4*)(xt + (size_t)row * DIM))[threadIdx.x] = v;
    uint2 h = make_uint2(h2u(__floats2half2_rn(v.x, v.y)),
                         h2u(__floats2half2_rn(v.z, v.w)));
    *(uint2*)(xth + (size_t)row * DIM + threadIdx.x * 4) = h;
}

__global__ void gather_s_kernel(const float* __restrict__ yt,
                                float* __restrict__ ys, __half* __restrict__ ysh)
{
    int row = blockIdx.x;
    int f = row / TS, t = row % TS;
    const float* src = (t == 0)
        ? yt + (size_t)((f & 63) * TT) * DIM
        : yt + (size_t)((t - 1) * TT + 1 + f) * DIM;
    float4 v = ((const float4*)src)[threadIdx.x];
    ((float4*)(ys + (size_t)row * DIM))[threadIdx.x] = v;
    uint2 h = make_uint2(h2u(__floats2half2_rn(v.x, v.y)),
                         h2u(__floats2half2_rn(v.z, v.w)));
    *(uint2*)(ysh + (size_t)row * DIM + threadIdx.x * 4) = h;
}

// -------------------- launch ----------------------------------------------
extern "C" void kernel_launch(void* const* d_in, const int* in_sizes, int n_in,
                              void* d_out, int out_size)
{
    const float* x      = (const float*)d_in[0];
    const float* Wqkv_t = (const float*)d_in[1];
    const float* Wo_t   = (const float*)d_in[2];
    const float* Wqkv_s = (const float*)d_in[3];
    const float* Wo_s   = (const float*)d_in[4];
    const float* E      = (const float*)d_in[5];
    const float* W1     = (const float*)d_in[6];
    const float* b1     = (const float*)d_in[7];
    const float* W2     = (const float*)d_in[8];
    const float* b2     = (const float*)d_in[9];
    float* out = (float*)d_out;

    float *xt, *yt, *ys, *ys2;
    __half *xth, *ysh, *qkvh, *attnh, *ys2h, *hh, *kprojh, *vprojh;
    __half *hQt, *hOt, *hQs, *hOs, *hW1, *hW2;
    cudaGetSymbolAddress((void**)&xt,     g_xt);
    cudaGetSymbolAddress((void**)&yt,     g_yt);
    cudaGetSymbolAddress((void**)&ys,     g_ys);
    cudaGetSymbolAddress((void**)&ys2,    g_ys2);
    cudaGetSymbolAddress((void**)&xth,    g_xth);
    cudaGetSymbolAddress((void**)&ysh,    g_ysh);
    cudaGetSymbolAddress((void**)&qkvh,   g_qkvh);
    cudaGetSymbolAddress((void**)&attnh,  g_attnh);
    cudaGetSymbolAddress((void**)&ys2h,   g_ys2h);
    cudaGetSymbolAddress((void**)&hh,     g_hh);
    cudaGetSymbolAddress((void**)&kprojh, g_kprojh);
    cudaGetSymbolAddress((void**)&vprojh, g_vprojh);
    cudaGetSymbolAddress((void**)&hQt,    g_hWqkv_t);
    cudaGetSymbolAddress((void**)&hOt,    g_hWo_t);
    cudaGetSymbolAddress((void**)&hQs,    g_hWqkv_s);
    cudaGetSymbolAddress((void**)&hOs,    g_hWo_s);
    cudaGetSymbolAddress((void**)&hW1,    g_hW1);
    cudaGetSymbolAddress((void**)&hW2,    g_hW2);

    const int ktT = (TT + 63) / 64;          // 5
    const int ktS = (KL + 63) / 64;          // 2
    const int qtT = (TT + 63) / 64;          // 5
    const int qtS = (TS + 63) / 64;          // 2
    const int smemT = 64 * (ktT * 64 + 8) * 2 + 2 * KVSZ * 2 + 64 * 4;   // ~60.7KB
    const int smemS = 64 * (ktS * 64 + 8) * 2 + 2 * KVSZ * 2 + 64 * 4;   // ~36KB
    cudaFuncSetAttribute(attn_h, cudaFuncAttributeMaxDynamicSharedMemorySize, smemT);

    // 0) convert weights to fp16
    auto cgrid = [](int n) { return (n / 8 + 255) / 256; };
    cvt16<<<cgrid(DIM * 3 * DIM), 256>>>(Wqkv_t, hQt, DIM * 3 * DIM);
    cvt16<<<cgrid(DIM * DIM), 256>>>(Wo_t, hOt, DIM * DIM);
    cvt16<<<cgrid(DIM * 3 * DIM), 256>>>(Wqkv_s, hQs, DIM * 3 * DIM);
    cvt16<<<cgrid(DIM * DIM), 256>>>(Wo_s, hOs, DIM * DIM);
    cvt16<<<cgrid(DIM * DFF), 256>>>(W1, hW1, DIM * DFF);
    cvt16<<<cgrid(DFF * DIM), 256>>>(W2, hW2, DFF * DIM);

    // 1) temporal token gather
    gather_t_kernel<<<RT, 128>>>(x, xt, xth);

    // 2) temporal QKV -> fp16 only
    gemm_h<<<dim3(3 * DIM / 128, RT / 64), 256>>>(
        xth, hQt, nullptr, nullptr, nullptr, qkvh, RT, 3 * DIM, DIM, 0);

    // 3) temporal attention (fp16)
    attn_h<<<dim3(qtT, PATCHES, HEADS), 256, smemT>>>(
        qkvh, 3 * DIM, qkvh + DIM, qkvh + 2 * DIM, 3 * DIM, attnh, TT, TT, ktT, 0.125f);

    // 4) Wo_t + residual
    gemm_h<<<dim3(DIM / 128, RT / 64), 256>>>(
        attnh, hOt, nullptr, xt, yt, nullptr, RT, DIM, DIM, FLAG_RES);

    // 5) spatial gather
    gather_s_kernel<<<RS, 128>>>(yt, ys, ysh);

    // 6) spatial QKV -> fp16 only
    gemm_h<<<dim3(3 * DIM / 128, RS / 64), 256>>>(
        ysh, hQs, nullptr, nullptr, nullptr, qkvh, RS, 3 * DIM, DIM, 0);

    // 7) Linformer K/V projection (fp16)
    linproj_h<<<dim3(FRAMES, DIM / 64, 8), 256>>>(qkvh, E, kprojh, vprojh);

    // 8) spatial attention (fp16, 2 query tiles)
    attn_h<<<dim3(qtS, FRAMES, HEADS), 256, smemS>>>(
        qkvh, 3 * DIM, kprojh, vprojh, DIM, attnh, TS, KL, ktS, 0.125f);

    // 9) Wo_s + residual
    gemm_h<<<dim3(DIM / 128, RS / 64), 256>>>(
        attnh, hOs, nullptr, ys, ys2, ys2h, RS, DIM, DIM, FLAG_RES);

    // 10) MLP up + bias + GELU (fp16-only output)
    gemm_h<<<dim3(DFF / 128, RS / 64), 256>>>(
        ys2h, hW1, b1, nullptr, nullptr, hh, RS, DFF, DIM, FLAG_BIAS | FLAG_GELU);

    // 11) MLP down + bias + residual -> final fp32 output
    gemm_h<<<dim3(DIM / 128, RS / 64), 256>>>(
        hh, hW2, b2, ys2, out, nullptr, RS, DIM, DFF, FLAG_BIAS | FLAG_RES);
}